// round 2
// baseline (speedup 1.0000x reference)
#include <cuda_runtime.h>

#define N_NODES 100000
#define N_EDGES 1600000
#define IN_CH   256
#define OUT_CH  128

// Scratch (static device globals — allocation-free per harness rules)
__device__ float g_deg[N_NODES];
__device__ float g_dinv[N_NODES];
__device__ __align__(16) float g_h[(size_t)N_NODES * OUT_CH];
__device__ int   g_is64;   // 1 if edge_index buffer is int64, 0 if int32

// ---------------------------------------------------------------------------
// Detect edge_index dtype. int64 little-endian with values < 2^31 has every
// odd 32-bit word == 0. For int32 data the odd words are random node indices;
// probability all 64 sampled odd words are 0 is ~(1e-5)^64 ~ 0.
// Deterministic: same input -> same flag.
// ---------------------------------------------------------------------------
__global__ void k_detect(const int* __restrict__ ei_words) {
    if (threadIdx.x == 0) {
        int all_zero = 1;
        for (int i = 0; i < 64; i++) {
            if (ei_words[2 * i + 1] != 0) { all_zero = 0; break; }
        }
        g_is64 = all_zero;
    }
}

__device__ __forceinline__ int edge_idx(const void* ei, int which, int e) {
    // which: 0 = row (source), 1 = col (destination)
    if (g_is64) {
        return (int)((const long long*)ei)[(size_t)which * N_EDGES + e];
    } else {
        return ((const int*)ei)[(size_t)which * N_EDGES + e];
    }
}

// ---------------------------------------------------------------------------
// Init: zero d_out (atomic accumulation target) and set deg = 1 (self loop)
// ---------------------------------------------------------------------------
__global__ void k_init(float* __restrict__ out) {
    int i = blockIdx.x * blockDim.x + threadIdx.x;
    if (i < N_NODES * 32) {
        ((float4*)out)[i] = make_float4(0.f, 0.f, 0.f, 0.f);
    }
    if (i < N_NODES) {
        g_deg[i] = 1.0f;
    }
}

// ---------------------------------------------------------------------------
// Degree: in-degree over col (edge_index[1]) — matches reference segment_sum
// ---------------------------------------------------------------------------
__global__ void k_deg(const void* __restrict__ ei) {
    int e = blockIdx.x * blockDim.x + threadIdx.x;
    if (e < N_EDGES) {
        int c = edge_idx(ei, 1, e);
        atomicAdd(&g_deg[c], 1.0f);
    }
}

__global__ void k_dinv() {
    int i = blockIdx.x * blockDim.x + threadIdx.x;
    if (i < N_NODES) {
        // deg >= 1 always (self loop), so this equals the reference's
        // where(deg>0, rsqrt(max(deg,1)), 0)
        g_dinv[i] = rsqrtf(g_deg[i]);
    }
}

// ---------------------------------------------------------------------------
// GEMM: h[M,128] = x[M,256] @ W[256,128], fp32
// Block: 256 threads, tile BM=64 x BN=128, K-chunks of 16.
// Thread tile: 8 rows x 4 cols (32 accumulators).
// ---------------------------------------------------------------------------
__global__ void __launch_bounds__(256) k_gemm(const float* __restrict__ x,
                                              const float* __restrict__ W,
                                              int M) {
    __shared__ float xs[16][65];    // [k][m], padded to dodge bank conflicts
    __shared__ float ws[16][128];   // [k][n]

    const int row0 = blockIdx.x * 64;
    const int tid  = threadIdx.x;
    const int tx   = tid & 31;      // col group: cols tx*4 .. tx*4+3
    const int ty   = tid >> 5;      // 0..7, rows ty + r*8

    float acc[8][4];
#pragma unroll
    for (int r = 0; r < 8; r++)
#pragma unroll
        for (int c = 0; c < 4; c++) acc[r][c] = 0.f;

    // x-tile load mapping: thread loads one float4 along K
    const int lm = tid >> 2;          // 0..63 (row within tile)
    const int lk = (tid & 3) * 4;     // k offset 0,4,8,12

    for (int k0 = 0; k0 < IN_CH; k0 += 16) {
        // load x tile (64 x 16)
        float4 xv = make_float4(0.f, 0.f, 0.f, 0.f);
        int gr = row0 + lm;
        if (gr < M)
            xv = *(const float4*)(x + (size_t)gr * IN_CH + k0 + lk);
        xs[lk + 0][lm] = xv.x;
        xs[lk + 1][lm] = xv.y;
        xs[lk + 2][lm] = xv.z;
        xs[lk + 3][lm] = xv.w;

        // load W tile (16 x 128) = 512 float4, 2 per thread
#pragma unroll
        for (int i = 0; i < 2; i++) {
            int idx = tid + i * 256;       // 0..511
            int k   = idx >> 5;            // 0..15
            int c   = (idx & 31) * 4;      // 0..124
            float4 wv = *(const float4*)(W + (size_t)(k0 + k) * OUT_CH + c);
            *(float4*)&ws[k][c] = wv;
        }
        __syncthreads();

#pragma unroll
        for (int kk = 0; kk < 16; kk++) {
            float4 b4 = *(const float4*)&ws[kk][tx * 4];
#pragma unroll
            for (int r = 0; r < 8; r++) {
                float a = xs[kk][ty + r * 8];   // broadcast within warp
                acc[r][0] += a * b4.x;
                acc[r][1] += a * b4.y;
                acc[r][2] += a * b4.z;
                acc[r][3] += a * b4.w;
            }
        }
        __syncthreads();
    }

#pragma unroll
    for (int r = 0; r < 8; r++) {
        int gr = row0 + ty + r * 8;
        if (gr < M) {
            float4 o = make_float4(acc[r][0], acc[r][1], acc[r][2], acc[r][3]);
            *(float4*)(g_h + (size_t)gr * OUT_CH + tx * 4) = o;
        }
    }
}

// ---------------------------------------------------------------------------
// Edge aggregation: one warp per edge.
// out[col] += h[row] * dinv[row]*dinv[col]   (128 channels, 4 per lane)
// ---------------------------------------------------------------------------
__global__ void __launch_bounds__(256) k_agg(const void* __restrict__ ei,
                                             float* __restrict__ out) {
    int gt   = blockIdx.x * blockDim.x + threadIdx.x;
    int e    = gt >> 5;
    int lane = gt & 31;
    if (e >= N_EDGES) return;

    int r = edge_idx(ei, 0, e);
    int c = edge_idx(ei, 1, e);
    float w = g_dinv[r] * g_dinv[c];

    float4 v = ((const float4*)(g_h + (size_t)r * OUT_CH))[lane];
    float* o = out + (size_t)c * OUT_CH + lane * 4;
    atomicAdd(o + 0, v.x * w);
    atomicAdd(o + 1, v.y * w);
    atomicAdd(o + 2, v.z * w);
    atomicAdd(o + 3, v.w * w);
}

// ---------------------------------------------------------------------------
// Epilogue: one warp per node.
// v = agg + h*dinv^2 (self loop) + b ; minmax-scale ; L2 normalize.
// ---------------------------------------------------------------------------
__global__ void __launch_bounds__(256) k_epi(const float* __restrict__ b,
                                             float* __restrict__ out) {
    int gt   = blockIdx.x * blockDim.x + threadIdx.x;
    int node = gt >> 5;
    if (node >= N_NODES) return;
    int lane = gt & 31;

    float s = g_dinv[node];
    s *= s;

    const float4 hv = ((const float4*)g_h)[(size_t)node * 32 + lane];
    float4       av = ((float4*)out)[(size_t)node * 32 + lane];
    const float4 bv = ((const float4*)b)[lane];

    float4 v;
    v.x = av.x + hv.x * s + bv.x;
    v.y = av.y + hv.y * s + bv.y;
    v.z = av.z + hv.z * s + bv.z;
    v.w = av.w + hv.w * s + bv.w;

    float mn = fminf(fminf(v.x, v.y), fminf(v.z, v.w));
    float mx = fmaxf(fmaxf(v.x, v.y), fmaxf(v.z, v.w));
#pragma unroll
    for (int o = 16; o; o >>= 1) {
        mn = fminf(mn, __shfl_xor_sync(0xffffffffu, mn, o));
        mx = fmaxf(mx, __shfl_xor_sync(0xffffffffu, mx, o));
    }

    float inv = 1.0f / (mx - mn);
    float4 z;
    z.x = (v.x - mn) * inv;
    z.y = (v.y - mn) * inv;
    z.z = (v.z - mn) * inv;
    z.w = (v.w - mn) * inv;

    float ss = z.x * z.x + z.y * z.y + z.z * z.z + z.w * z.w;
#pragma unroll
    for (int o = 16; o; o >>= 1)
        ss += __shfl_xor_sync(0xffffffffu, ss, o);

    float rn = 1.0f / fmaxf(sqrtf(ss), 1e-12f);
    z.x *= rn; z.y *= rn; z.z *= rn; z.w *= rn;

    ((float4*)out)[(size_t)node * 32 + lane] = z;
}

// ---------------------------------------------------------------------------
extern "C" void kernel_launch(void* const* d_in, const int* in_sizes, int n_in,
                              void* d_out, int out_size) {
    const float* x   = (const float*)d_in[0];
    const void*  ei  = d_in[1];
    const float* W   = (const float*)d_in[2];
    const float* b   = (const float*)d_in[3];
    float*       out = (float*)d_out;

    (void)in_sizes; (void)n_in; (void)out_size;

    k_detect<<<1, 32>>>((const int*)ei);
    k_init  <<<(N_NODES * 32 + 255) / 256, 256>>>(out);
    k_deg   <<<(N_EDGES + 255) / 256, 256>>>(ei);
    k_dinv  <<<(N_NODES + 255) / 256, 256>>>();
    k_gemm  <<<(N_NODES + 63) / 64, 256>>>(x, W, N_NODES);
    k_agg   <<<(size_t)N_EDGES * 32 / 256, 256>>>(ei, out);
    k_epi   <<<(N_NODES * 32 + 255) / 256, 256>>>(b, out);
}

// round 3
// speedup vs baseline: 1.3347x; 1.3347x over previous
#include <cuda_runtime.h>

#define N_NODES 100000
#define N_EDGES 1600000
#define IN_CH   256
#define OUT_CH  128

// Scratch (static device globals — allocation-free per harness rules)
__device__ float g_deg[N_NODES];
__device__ float g_dinv[N_NODES];
__device__ __align__(16) float g_h[(size_t)N_NODES * OUT_CH];
__device__ int   g_is64;   // 1 if edge_index buffer is int64, 0 if int32

// ---------------------------------------------------------------------------
// Detect edge_index dtype. int64 little-endian with values < 2^31 has every
// odd 32-bit word == 0. Deterministic.
// ---------------------------------------------------------------------------
__global__ void k_detect(const int* __restrict__ ei_words) {
    if (threadIdx.x == 0) {
        int all_zero = 1;
        for (int i = 0; i < 64; i++) {
            if (ei_words[2 * i + 1] != 0) { all_zero = 0; break; }
        }
        g_is64 = all_zero;
    }
}

__device__ __forceinline__ int edge_idx(const void* ei, int which, int e) {
    if (g_is64) {
        return (int)((const long long*)ei)[(size_t)which * N_EDGES + e];
    } else {
        return ((const int*)ei)[(size_t)which * N_EDGES + e];
    }
}

// ---------------------------------------------------------------------------
// Init: zero d_out (atomic target) and set deg = 1 (self loop)
// ---------------------------------------------------------------------------
__global__ void k_init(float* __restrict__ out) {
    int i = blockIdx.x * blockDim.x + threadIdx.x;
    if (i < N_NODES * 32) {
        ((float4*)out)[i] = make_float4(0.f, 0.f, 0.f, 0.f);
    }
    if (i < N_NODES) {
        g_deg[i] = 1.0f;
    }
}

// ---------------------------------------------------------------------------
// Degree: in-degree over col (edge_index[1])
// ---------------------------------------------------------------------------
__global__ void k_deg(const void* __restrict__ ei) {
    int e = blockIdx.x * blockDim.x + threadIdx.x;
    if (e < N_EDGES) {
        int c = edge_idx(ei, 1, e);
        atomicAdd(&g_deg[c], 1.0f);
    }
}

__global__ void k_dinv() {
    int i = blockIdx.x * blockDim.x + threadIdx.x;
    if (i < N_NODES) {
        g_dinv[i] = rsqrtf(g_deg[i]);   // deg >= 1 always (self loop)
    }
}

// ---------------------------------------------------------------------------
// GEMM: h[M,128] = x[M,256] @ W[256,128], fp32 SIMT.
// Block 256 threads, tile BM=64 x BN=128, K-chunk 16.
// Thread tile: 8 CONSECUTIVE rows (ty*8..ty*8+7) x 4 cols -> vector LDS.
// ---------------------------------------------------------------------------
__global__ void __launch_bounds__(256) k_gemm(const float* __restrict__ x,
                                              const float* __restrict__ W,
                                              int M) {
    // stride 68 floats = 272B: 16B-aligned rows AND 4-bank rotation per k-row
    __shared__ __align__(16) float xs[16 * 68];
    __shared__ __align__(16) float ws[16][128];

    const int row0 = blockIdx.x * 64;
    const int tid  = threadIdx.x;
    const int tx   = tid & 31;      // col group: cols tx*4 .. tx*4+3
    const int ty   = tid >> 5;      // row group: rows ty*8 .. ty*8+7

    float acc[8][4];
#pragma unroll
    for (int r = 0; r < 8; r++)
#pragma unroll
        for (int c = 0; c < 4; c++) acc[r][c] = 0.f;

    const int lm = tid >> 2;          // 0..63 (row within tile)
    const int lk = (tid & 3) * 4;     // k offset 0,4,8,12

    for (int k0 = 0; k0 < IN_CH; k0 += 16) {
        // load x tile (64 rows x 16 k) transposed into xs[k][m]
        float4 xv = make_float4(0.f, 0.f, 0.f, 0.f);
        int gr = row0 + lm;
        if (gr < M)
            xv = *(const float4*)(x + (size_t)gr * IN_CH + k0 + lk);
        xs[(lk + 0) * 68 + lm] = xv.x;
        xs[(lk + 1) * 68 + lm] = xv.y;
        xs[(lk + 2) * 68 + lm] = xv.z;
        xs[(lk + 3) * 68 + lm] = xv.w;

        // load W tile (16 x 128) = 512 float4, 2 per thread
#pragma unroll
        for (int i = 0; i < 2; i++) {
            int idx = tid + i * 256;       // 0..511
            int k   = idx >> 5;            // 0..15
            int c   = (idx & 31) * 4;      // 0..124
            *(float4*)&ws[k][c] = *(const float4*)(W + (size_t)(k0 + k) * OUT_CH + c);
        }
        __syncthreads();

#pragma unroll
        for (int kk = 0; kk < 16; kk++) {
            float4 b4  = *(const float4*)&ws[kk][tx * 4];
            float4 alo = *(const float4*)&xs[kk * 68 + ty * 8];      // broadcast
            float4 ahi = *(const float4*)&xs[kk * 68 + ty * 8 + 4];  // broadcast
            float a[8] = {alo.x, alo.y, alo.z, alo.w, ahi.x, ahi.y, ahi.z, ahi.w};
#pragma unroll
            for (int r = 0; r < 8; r++) {
                acc[r][0] += a[r] * b4.x;
                acc[r][1] += a[r] * b4.y;
                acc[r][2] += a[r] * b4.z;
                acc[r][3] += a[r] * b4.w;
            }
        }
        __syncthreads();
    }

#pragma unroll
    for (int r = 0; r < 8; r++) {
        int gr = row0 + ty * 8 + r;
        if (gr < M) {
            float4 o = make_float4(acc[r][0], acc[r][1], acc[r][2], acc[r][3]);
            *(float4*)(g_h + (size_t)gr * OUT_CH + tx * 4) = o;
        }
    }
}

// ---------------------------------------------------------------------------
// Edge aggregation: one warp per edge, ONE vector reduction per lane.
// out[col] += h[row] * dinv[row]*dinv[col]
// ---------------------------------------------------------------------------
__global__ void __launch_bounds__(256) k_agg(const void* __restrict__ ei,
                                             float* __restrict__ out) {
    int gt   = blockIdx.x * blockDim.x + threadIdx.x;
    int e    = gt >> 5;
    int lane = gt & 31;
    if (e >= N_EDGES) return;

    int r = edge_idx(ei, 0, e);
    int c = edge_idx(ei, 1, e);
    float w = g_dinv[r] * g_dinv[c];

    float4 v = ((const float4*)(g_h + (size_t)r * OUT_CH))[lane];
    v.x *= w; v.y *= w; v.z *= w; v.w *= w;

    float* o = out + (size_t)c * OUT_CH + lane * 4;
    // one REDG.128 instead of four REDG.32
    asm volatile("red.global.add.v4.f32 [%0], {%1, %2, %3, %4};"
                 :: "l"(o), "f"(v.x), "f"(v.y), "f"(v.z), "f"(v.w)
                 : "memory");
}

// ---------------------------------------------------------------------------
// Epilogue: one warp per node.
// v = agg + h*dinv^2 (self loop) + b ; minmax-scale ; L2 normalize.
// ---------------------------------------------------------------------------
__global__ void __launch_bounds__(256) k_epi(const float* __restrict__ b,
                                             float* __restrict__ out) {
    int gt   = blockIdx.x * blockDim.x + threadIdx.x;
    int node = gt >> 5;
    if (node >= N_NODES) return;
    int lane = gt & 31;

    float s = g_dinv[node];
    s *= s;

    const float4 hv = ((const float4*)g_h)[(size_t)node * 32 + lane];
    float4       av = ((float4*)out)[(size_t)node * 32 + lane];
    const float4 bv = ((const float4*)b)[lane];

    float4 v;
    v.x = av.x + hv.x * s + bv.x;
    v.y = av.y + hv.y * s + bv.y;
    v.z = av.z + hv.z * s + bv.z;
    v.w = av.w + hv.w * s + bv.w;

    float mn = fminf(fminf(v.x, v.y), fminf(v.z, v.w));
    float mx = fmaxf(fmaxf(v.x, v.y), fmaxf(v.z, v.w));
#pragma unroll
    for (int o = 16; o; o >>= 1) {
        mn = fminf(mn, __shfl_xor_sync(0xffffffffu, mn, o));
        mx = fmaxf(mx, __shfl_xor_sync(0xffffffffu, mx, o));
    }

    float inv = 1.0f / (mx - mn);
    float4 z;
    z.x = (v.x - mn) * inv;
    z.y = (v.y - mn) * inv;
    z.z = (v.z - mn) * inv;
    z.w = (v.w - mn) * inv;

    float ss = z.x * z.x + z.y * z.y + z.z * z.z + z.w * z.w;
#pragma unroll
    for (int o = 16; o; o >>= 1)
        ss += __shfl_xor_sync(0xffffffffu, ss, o);

    float rn = 1.0f / fmaxf(sqrtf(ss), 1e-12f);
    z.x *= rn; z.y *= rn; z.z *= rn; z.w *= rn;

    ((float4*)out)[(size_t)node * 32 + lane] = z;
}

// ---------------------------------------------------------------------------
extern "C" void kernel_launch(void* const* d_in, const int* in_sizes, int n_in,
                              void* d_out, int out_size) {
    const float* x   = (const float*)d_in[0];
    const void*  ei  = d_in[1];
    const float* W   = (const float*)d_in[2];
    const float* b   = (const float*)d_in[3];
    float*       out = (float*)d_out;

    (void)in_sizes; (void)n_in; (void)out_size;

    k_detect<<<1, 32>>>((const int*)ei);
    k_init  <<<(N_NODES * 32 + 255) / 256, 256>>>(out);
    k_deg   <<<(N_EDGES + 255) / 256, 256>>>(ei);
    k_dinv  <<<(N_NODES + 255) / 256, 256>>>();
    k_gemm  <<<(N_NODES + 63) / 64, 256>>>(x, W, N_NODES);
    k_agg   <<<(size_t)N_EDGES * 32 / 256, 256>>>(ei, out);
    k_epi   <<<(N_NODES * 32 + 255) / 256, 256>>>(b, out);
}

// round 5
// speedup vs baseline: 1.6053x; 1.2028x over previous
#include <cuda_runtime.h>
#include <cstdint>

#define N_NODES 100000
#define N_EDGES 1600000
#define IN_CH   256
#define OUT_CH  128

// ---------------------------------------------------------------------------
// Scratch (static device globals — allocation-free per harness rules)
// ---------------------------------------------------------------------------
__device__ float g_deg[N_NODES];
__device__ float g_dinv[N_NODES];
__device__ __align__(16) float g_h[(size_t)N_NODES * OUT_CH];   // h * dinv[row]
__device__ __align__(16) float g_Bhi[OUT_CH * IN_CH];           // W^T hi (tf32), [n][k]
__device__ __align__(16) float g_Blo[OUT_CH * IN_CH];           // W^T lo (tf32), [n][k]
__device__ int   g_is64;

// ---------------------------------------------------------------------------
// tf32 helpers
// ---------------------------------------------------------------------------
__device__ __forceinline__ void tf32_split(float v, uint32_t& hi, uint32_t& lo) {
    asm("cvt.rna.tf32.f32 %0, %1;" : "=r"(hi) : "f"(v));
    float r = v - __uint_as_float(hi);
    asm("cvt.rna.tf32.f32 %0, %1;" : "=r"(lo) : "f"(r));
}
__device__ __forceinline__ uint32_t tf32_hi(float v) {
    uint32_t h;
    asm("cvt.rna.tf32.f32 %0, %1;" : "=r"(h) : "f"(v));
    return h;
}

// mma.sync m16n8k8 tf32: D += A*B (fp32 accumulate)
__device__ __forceinline__ void mma_tf32(float4& d,
                                         uint32_t a0, uint32_t a1, uint32_t a2, uint32_t a3,
                                         uint32_t b0, uint32_t b1) {
    asm volatile("mma.sync.aligned.m16n8k8.row.col.f32.tf32.tf32.f32 "
                 "{%0,%1,%2,%3}, {%4,%5,%6,%7}, {%8,%9}, {%0,%1,%2,%3};"
                 : "+f"(d.x), "+f"(d.y), "+f"(d.z), "+f"(d.w)
                 : "r"(a0), "r"(a1), "r"(a2), "r"(a3), "r"(b0), "r"(b1));
}

// ---------------------------------------------------------------------------
// Detect edge_index dtype (int64 vs int32). Deterministic.
// ---------------------------------------------------------------------------
__global__ void k_detect(const int* __restrict__ ei_words) {
    if (threadIdx.x == 0) {
        int all_zero = 1;
        for (int i = 0; i < 64; i++)
            if (ei_words[2 * i + 1] != 0) { all_zero = 0; break; }
        g_is64 = all_zero;
    }
}
__device__ __forceinline__ int edge_idx(const void* ei, int which, int e) {
    if (g_is64) return (int)((const long long*)ei)[(size_t)which * N_EDGES + e];
    return ((const int*)ei)[(size_t)which * N_EDGES + e];
}

// ---------------------------------------------------------------------------
__global__ void k_init(float* __restrict__ out) {
    int i = blockIdx.x * blockDim.x + threadIdx.x;
    if (i < N_NODES * 32) ((float4*)out)[i] = make_float4(0.f, 0.f, 0.f, 0.f);
    if (i < N_NODES) g_deg[i] = 1.0f;
}

__global__ void k_deg(const void* __restrict__ ei) {
    int e = blockIdx.x * blockDim.x + threadIdx.x;
    if (e < N_EDGES) atomicAdd(&g_deg[edge_idx(ei, 1, e)], 1.0f);
}

__global__ void k_dinv() {
    int i = blockIdx.x * blockDim.x + threadIdx.x;
    if (i < N_NODES) g_dinv[i] = rsqrtf(g_deg[i]);   // deg >= 1 (self loop)
}

// ---------------------------------------------------------------------------
// Transpose + tf32-split W[256][128] -> g_Bhi/g_Blo[n][k]
// ---------------------------------------------------------------------------
__global__ void k_wsplit(const float* __restrict__ W) {
    int g = blockIdx.x * blockDim.x + threadIdx.x;
    if (g >= IN_CH * OUT_CH) return;
    int k = g >> 7;          // 0..255
    int n = g & 127;         // 0..127
    uint32_t hi, lo;
    tf32_split(W[(size_t)k * OUT_CH + n], hi, lo);
    g_Bhi[(size_t)n * IN_CH + k] = __uint_as_float(hi);
    g_Blo[(size_t)n * IN_CH + k] = __uint_as_float(lo);
}

// ---------------------------------------------------------------------------
// Tensor-core GEMM via mma.sync (tf32, 3x split):
//   g_h[M,128] = (x[M,256] @ W[256,128]) * dinv[row]
// CTA tile 128x128, 8 warps as 2(M) x 4(N), warp tile 64x32.
// K staged in smem chunks of 32, row stride 36 floats (bank-bijective).
// ---------------------------------------------------------------------------
#define XS_STRIDE 36
#define GSM_BYTES (3 * 128 * XS_STRIDE * 4)

__global__ void __launch_bounds__(256, 1) k_gemm_mma(const float* __restrict__ x, int M) {
    extern __shared__ float smem[];
    float* xs = smem;                      // x chunk  [128 m][36]
    float* wh = xs + 128 * XS_STRIDE;      // Bhi chunk [128 n][36]
    float* wl = wh + 128 * XS_STRIDE;      // Blo chunk [128 n][36]

    const int tid    = threadIdx.x;
    const int wid    = tid >> 5;
    const int lane   = tid & 31;
    const int gq     = lane >> 2;          // group id 0..7
    const int tq     = lane & 3;           // thread-in-group 0..3
    const int warp_m = wid >> 2;           // 0..1
    const int warp_n = wid & 3;            // 0..3
    const int row0   = blockIdx.x * 128;

    float4 acc[4][4];
#pragma unroll
    for (int i = 0; i < 4; i++)
#pragma unroll
        for (int j = 0; j < 4; j++) acc[i][j] = make_float4(0.f, 0.f, 0.f, 0.f);

    for (int c = 0; c < 8; c++) {
        // stage x chunk: 128 rows x 32 k -> 4 float4/thread
#pragma unroll
        for (int i = 0; i < 4; i++) {
            int idx = tid + i * 256;       // 0..1023
            int m   = idx >> 3;
            int f4  = idx & 7;
            int gr  = row0 + m;
            float4 v = make_float4(0.f, 0.f, 0.f, 0.f);
            if (gr < M)
                v = *(const float4*)(x + (size_t)gr * IN_CH + c * 32 + f4 * 4);
            *(float4*)(xs + m * XS_STRIDE + f4 * 4) = v;
        }
        // stage B chunk (pre-split): 128 n x 32 k, hi + lo
#pragma unroll
        for (int i = 0; i < 4; i++) {
            int idx = tid + i * 256;
            int n   = idx >> 3;
            int f4  = idx & 7;
            size_t gofs = (size_t)n * IN_CH + c * 32 + f4 * 4;
            *(float4*)(wh + n * XS_STRIDE + f4 * 4) = *(const float4*)(g_Bhi + gofs);
            *(float4*)(wl + n * XS_STRIDE + f4 * 4) = *(const float4*)(g_Blo + gofs);
        }
        __syncthreads();

#pragma unroll
        for (int s = 0; s < 4; s++) {      // k-steps of 8
            const int k0 = s * 8;

            // B fragments for this warp's 4 n-frags (hi & lo)
            uint32_t b0h[4], b1h[4], b0l[4], b1l[4];
#pragma unroll
            for (int nf = 0; nf < 4; nf++) {
                int n = warp_n * 32 + nf * 8 + gq;
                b0h[nf] = __float_as_uint(wh[n * XS_STRIDE + k0 + tq]);
                b1h[nf] = __float_as_uint(wh[n * XS_STRIDE + k0 + tq + 4]);
                b0l[nf] = __float_as_uint(wl[n * XS_STRIDE + k0 + tq]);
                b1l[nf] = __float_as_uint(wl[n * XS_STRIDE + k0 + tq + 4]);
            }

#pragma unroll
            for (int mf = 0; mf < 4; mf++) {
                int rbase = warp_m * 64 + mf * 16;
                float a0f = xs[(rbase + gq)     * XS_STRIDE + k0 + tq];
                float a1f = xs[(rbase + gq + 8) * XS_STRIDE + k0 + tq];
                float a2f = xs[(rbase + gq)     * XS_STRIDE + k0 + tq + 4];
                float a3f = xs[(rbase + gq + 8) * XS_STRIDE + k0 + tq + 4];
                uint32_t a0h, a0l, a1h, a1l, a2h, a2l, a3h, a3l;
                tf32_split(a0f, a0h, a0l); tf32_split(a1f, a1h, a1l);
                tf32_split(a2f, a2h, a2l); tf32_split(a3f, a3h, a3l);

#pragma unroll
                for (int nf = 0; nf < 4; nf++) {
                    mma_tf32(acc[mf][nf], a0h, a1h, a2h, a3h, b0h[nf], b1h[nf]);
                    mma_tf32(acc[mf][nf], a0h, a1h, a2h, a3h, b0l[nf], b1l[nf]);
                    mma_tf32(acc[mf][nf], a0l, a1l, a2l, a3l, b0h[nf], b1h[nf]);
                }
            }
        }
        __syncthreads();
    }

    // Store: d0,d1 -> (row g, cols 2t,2t+1); d2,d3 -> (row g+8). Scale by dinv.
#pragma unroll
    for (int mf = 0; mf < 4; mf++) {
        int rA = row0 + warp_m * 64 + mf * 16 + gq;
        int rB = rA + 8;
        float dvA = (rA < M) ? g_dinv[rA] : 0.f;
        float dvB = (rB < M) ? g_dinv[rB] : 0.f;
#pragma unroll
        for (int nf = 0; nf < 4; nf++) {
            int col = warp_n * 32 + nf * 8 + tq * 2;
            if (rA < M) {
                float2 v = make_float2(acc[mf][nf].x * dvA, acc[mf][nf].y * dvA);
                *(float2*)(g_h + (size_t)rA * OUT_CH + col) = v;
            }
            if (rB < M) {
                float2 v = make_float2(acc[mf][nf].z * dvB, acc[mf][nf].w * dvB);
                *(float2*)(g_h + (size_t)rB * OUT_CH + col) = v;
            }
        }
    }
}

// ---------------------------------------------------------------------------
// Edge aggregation: one warp per edge, one REDG.128 per lane.
// g_h already holds h*dinv[row]; out[col] += g_h[row] * dinv[col]
// ---------------------------------------------------------------------------
__global__ void __launch_bounds__(256) k_agg(const void* __restrict__ ei,
                                             float* __restrict__ out) {
    int gt   = blockIdx.x * blockDim.x + threadIdx.x;
    int e    = gt >> 5;
    int lane = gt & 31;
    if (e >= N_EDGES) return;

    int r = edge_idx(ei, 0, e);
    int c = edge_idx(ei, 1, e);
    float w = g_dinv[c];

    float4 v = ((const float4*)(g_h + (size_t)r * OUT_CH))[lane];
    v.x *= w; v.y *= w; v.z *= w; v.w *= w;

    float* o = out + (size_t)c * OUT_CH + lane * 4;
    asm volatile("red.global.add.v4.f32 [%0], {%1, %2, %3, %4};"
                 :: "l"(o), "f"(v.x), "f"(v.y), "f"(v.z), "f"(v.w) : "memory");
}

// ---------------------------------------------------------------------------
// Epilogue: one warp per node.
// v = agg + g_h[node]*dinv[node] (self loop; g_h = h*dinv) + b
// ---------------------------------------------------------------------------
__global__ void __launch_bounds__(256) k_epi(const float* __restrict__ b,
                                             float* __restrict__ out) {
    int gt   = blockIdx.x * blockDim.x + threadIdx.x;
    int node = gt >> 5;
    if (node >= N_NODES) return;
    int lane = gt & 31;

    float s = g_dinv[node];

    const float4 hv = ((const float4*)g_h)[(size_t)node * 32 + lane];
    float4       av = ((float4*)out)[(size_t)node * 32 + lane];
    const float4 bv = ((const float4*)b)[lane];

    float4 v;
    v.x = av.x + hv.x * s + bv.x;
    v.y = av.y + hv.y * s + bv.y;
    v.z = av.z + hv.z * s + bv.z;
    v.w = av.w + hv.w * s + bv.w;

    float mn = fminf(fminf(v.x, v.y), fminf(v.z, v.w));
    float mx = fmaxf(fmaxf(v.x, v.y), fmaxf(v.z, v.w));
#pragma unroll
    for (int o = 16; o; o >>= 1) {
        mn = fminf(mn, __shfl_xor_sync(0xffffffffu, mn, o));
        mx = fmaxf(mx, __shfl_xor_sync(0xffffffffu, mx, o));
    }

    float inv = 1.0f / (mx - mn);
    float4 z;
    z.x = (v.x - mn) * inv;
    z.y = (v.y - mn) * inv;
    z.z = (v.z - mn) * inv;
    z.w = (v.w - mn) * inv;

    float ss = z.x * z.x + z.y * z.y + z.z * z.z + z.w * z.w;
#pragma unroll
    for (int o = 16; o; o >>= 1)
        ss += __shfl_xor_sync(0xffffffffu, ss, o);

    float rn = 1.0f / fmaxf(sqrtf(ss), 1e-12f);
    z.x *= rn; z.y *= rn; z.z *= rn; z.w *= rn;

    ((float4*)out)[(size_t)node * 32 + lane] = z;
}

// ---------------------------------------------------------------------------
extern "C" void kernel_launch(void* const* d_in, const int* in_sizes, int n_in,
                              void* d_out, int out_size) {
    const float* x   = (const float*)d_in[0];
    const void*  ei  = d_in[1];
    const float* W   = (const float*)d_in[2];
    const float* b   = (const float*)d_in[3];
    float*       out = (float*)d_out;

    (void)in_sizes; (void)n_in; (void)out_size;

    cudaFuncSetAttribute(k_gemm_mma, cudaFuncAttributeMaxDynamicSharedMemorySize, GSM_BYTES);

    k_detect<<<1, 32>>>((const int*)ei);
    k_init  <<<(N_NODES * 32 + 255) / 256, 256>>>(out);
    k_deg   <<<(N_EDGES + 255) / 256, 256>>>(ei);
    k_dinv  <<<(N_NODES + 255) / 256, 256>>>();
    k_wsplit<<<(IN_CH * OUT_CH + 255) / 256, 256>>>(W);
    k_gemm_mma<<<(N_NODES + 127) / 128, 256, GSM_BYTES>>>(x, N_NODES);
    k_agg   <<<(size_t)N_EDGES * 32 / 256, 256>>>(ei, out);
    k_epi   <<<(N_NODES * 32 + 255) / 256, 256>>>(b, out);
}

// round 6
// speedup vs baseline: 2.4224x; 1.5090x over previous
#include <cuda_runtime.h>
#include <cstdint>

#define N_NODES 100000
#define N_EDGES 1600000
#define IN_CH   256
#define OUT_CH  128
#define NB      ((N_NODES + 255) / 256)   // 391

// ---------------------------------------------------------------------------
// Scratch (static device globals — allocation-free per harness rules)
// ---------------------------------------------------------------------------
__device__ float g_deg[N_NODES];
__device__ float g_dinv[N_NODES];
__device__ __align__(16) float g_h[(size_t)N_NODES * OUT_CH];   // h * dinv[row]
__device__ __align__(16) float g_Bhi[OUT_CH * IN_CH];           // W^T hi (tf32), [n][k]
__device__ __align__(16) float g_Blo[OUT_CH * IN_CH];           // W^T lo (tf32), [n][k]
__device__ int   g_is64;
__device__ int   g_bsum[NB];
__device__ int   g_boff[NB];
__device__ int   g_off[N_NODES];       // CSR start per destination node
__device__ int   g_cursor[N_NODES];    // scatter cursors (mutable copy)
__device__ int   g_src[N_EDGES];       // CSR source indices

// ---------------------------------------------------------------------------
// tf32 helpers
// ---------------------------------------------------------------------------
__device__ __forceinline__ void tf32_split(float v, uint32_t& hi, uint32_t& lo) {
    asm("cvt.rna.tf32.f32 %0, %1;" : "=r"(hi) : "f"(v));
    float r = v - __uint_as_float(hi);
    asm("cvt.rna.tf32.f32 %0, %1;" : "=r"(lo) : "f"(r));
}

__device__ __forceinline__ void mma_tf32(float4& d,
                                         uint32_t a0, uint32_t a1, uint32_t a2, uint32_t a3,
                                         uint32_t b0, uint32_t b1) {
    asm volatile("mma.sync.aligned.m16n8k8.row.col.f32.tf32.tf32.f32 "
                 "{%0,%1,%2,%3}, {%4,%5,%6,%7}, {%8,%9}, {%0,%1,%2,%3};"
                 : "+f"(d.x), "+f"(d.y), "+f"(d.z), "+f"(d.w)
                 : "r"(a0), "r"(a1), "r"(a2), "r"(a3), "r"(b0), "r"(b1));
}

// ---------------------------------------------------------------------------
// Detect edge_index dtype (int64 vs int32). Deterministic.
// ---------------------------------------------------------------------------
__global__ void k_detect(const int* __restrict__ ei_words) {
    if (threadIdx.x == 0) {
        int all_zero = 1;
        for (int i = 0; i < 64; i++)
            if (ei_words[2 * i + 1] != 0) { all_zero = 0; break; }
        g_is64 = all_zero;
    }
}
__device__ __forceinline__ int edge_idx(const void* ei, int which, int e) {
    if (g_is64) return (int)((const long long*)ei)[(size_t)which * N_EDGES + e];
    return ((const int*)ei)[(size_t)which * N_EDGES + e];
}

// ---------------------------------------------------------------------------
__global__ void k_deginit() {
    int i = blockIdx.x * blockDim.x + threadIdx.x;
    if (i < N_NODES) g_deg[i] = 1.0f;     // self loop
}

__global__ void k_deg(const void* __restrict__ ei) {
    int e = blockIdx.x * blockDim.x + threadIdx.x;
    if (e < N_EDGES) atomicAdd(&g_deg[edge_idx(ei, 1, e)], 1.0f);
}

// ---------------------------------------------------------------------------
// 3-pass exclusive scan of in-degree counts (deg-1) -> g_off, g_cursor; dinv.
// ---------------------------------------------------------------------------
__global__ void k_scan1() {
    __shared__ int sm[256];
    int tid = threadIdx.x;
    int i = blockIdx.x * 256 + tid;
    sm[tid] = (i < N_NODES) ? ((int)g_deg[i] - 1) : 0;
    __syncthreads();
#pragma unroll
    for (int o = 128; o; o >>= 1) {
        if (tid < o) sm[tid] += sm[tid + o];
        __syncthreads();
    }
    if (tid == 0) g_bsum[blockIdx.x] = sm[0];
}

__global__ void k_scan2() {
    __shared__ int sm[512];
    int t = threadIdx.x;
    int v0 = (t < NB) ? g_bsum[t] : 0;
    sm[t] = v0;
    __syncthreads();
#pragma unroll
    for (int o = 1; o < 512; o <<= 1) {
        int v = (t >= o) ? sm[t - o] : 0;
        __syncthreads();
        sm[t] += v;
        __syncthreads();
    }
    if (t < NB) g_boff[t] = sm[t] - v0;   // exclusive
}

__global__ void k_scan3() {
    __shared__ int sm[256];
    int tid = threadIdx.x;
    int i = blockIdx.x * 256 + tid;
    int cnt = (i < N_NODES) ? ((int)g_deg[i] - 1) : 0;
    sm[tid] = cnt;
    __syncthreads();
#pragma unroll
    for (int o = 1; o < 256; o <<= 1) {
        int v = (tid >= o) ? sm[tid - o] : 0;
        __syncthreads();
        sm[tid] += v;
        __syncthreads();
    }
    if (i < N_NODES) {
        int excl = sm[tid] - cnt + g_boff[blockIdx.x];
        g_off[i]    = excl;
        g_cursor[i] = excl;
        g_dinv[i]   = rsqrtf(g_deg[i]);
    }
}

// ---------------------------------------------------------------------------
// Scatter edges into CSR buckets by destination.
// ---------------------------------------------------------------------------
__global__ void k_scatter(const void* __restrict__ ei) {
    int e = blockIdx.x * blockDim.x + threadIdx.x;
    if (e >= N_EDGES) return;
    int c = edge_idx(ei, 1, e);
    int r = edge_idx(ei, 0, e);
    int pos = atomicAdd(&g_cursor[c], 1);
    g_src[pos] = r;
}

// ---------------------------------------------------------------------------
// Transpose + tf32-split W[256][128] -> g_Bhi/g_Blo[n][k]
// ---------------------------------------------------------------------------
__global__ void k_wsplit(const float* __restrict__ W) {
    int g = blockIdx.x * blockDim.x + threadIdx.x;
    if (g >= IN_CH * OUT_CH) return;
    int k = g >> 7;
    int n = g & 127;
    uint32_t hi, lo;
    tf32_split(W[(size_t)k * OUT_CH + n], hi, lo);
    g_Bhi[(size_t)n * IN_CH + k] = __uint_as_float(hi);
    g_Blo[(size_t)n * IN_CH + k] = __uint_as_float(lo);
}

// ---------------------------------------------------------------------------
// Tensor-core GEMM via mma.sync (tf32, 3x split):
//   g_h[M,128] = (x[M,256] @ W[256,128]) * dinv[row]
// ---------------------------------------------------------------------------
#define XS_STRIDE 36
#define GSM_BYTES (3 * 128 * XS_STRIDE * 4)

__global__ void __launch_bounds__(256, 1) k_gemm_mma(const float* __restrict__ x, int M) {
    extern __shared__ float smem[];
    float* xs = smem;
    float* wh = xs + 128 * XS_STRIDE;
    float* wl = wh + 128 * XS_STRIDE;

    const int tid    = threadIdx.x;
    const int wid    = tid >> 5;
    const int lane   = tid & 31;
    const int gq     = lane >> 2;
    const int tq     = lane & 3;
    const int warp_m = wid >> 2;
    const int warp_n = wid & 3;
    const int row0   = blockIdx.x * 128;

    float4 acc[4][4];
#pragma unroll
    for (int i = 0; i < 4; i++)
#pragma unroll
        for (int j = 0; j < 4; j++) acc[i][j] = make_float4(0.f, 0.f, 0.f, 0.f);

    for (int c = 0; c < 8; c++) {
#pragma unroll
        for (int i = 0; i < 4; i++) {
            int idx = tid + i * 256;
            int m   = idx >> 3;
            int f4  = idx & 7;
            int gr  = row0 + m;
            float4 v = make_float4(0.f, 0.f, 0.f, 0.f);
            if (gr < M)
                v = *(const float4*)(x + (size_t)gr * IN_CH + c * 32 + f4 * 4);
            *(float4*)(xs + m * XS_STRIDE + f4 * 4) = v;
        }
#pragma unroll
        for (int i = 0; i < 4; i++) {
            int idx = tid + i * 256;
            int n   = idx >> 3;
            int f4  = idx & 7;
            size_t gofs = (size_t)n * IN_CH + c * 32 + f4 * 4;
            *(float4*)(wh + n * XS_STRIDE + f4 * 4) = *(const float4*)(g_Bhi + gofs);
            *(float4*)(wl + n * XS_STRIDE + f4 * 4) = *(const float4*)(g_Blo + gofs);
        }
        __syncthreads();

#pragma unroll
        for (int s = 0; s < 4; s++) {
            const int k0 = s * 8;
            uint32_t b0h[4], b1h[4], b0l[4], b1l[4];
#pragma unroll
            for (int nf = 0; nf < 4; nf++) {
                int n = warp_n * 32 + nf * 8 + gq;
                b0h[nf] = __float_as_uint(wh[n * XS_STRIDE + k0 + tq]);
                b1h[nf] = __float_as_uint(wh[n * XS_STRIDE + k0 + tq + 4]);
                b0l[nf] = __float_as_uint(wl[n * XS_STRIDE + k0 + tq]);
                b1l[nf] = __float_as_uint(wl[n * XS_STRIDE + k0 + tq + 4]);
            }
#pragma unroll
            for (int mf = 0; mf < 4; mf++) {
                int rbase = warp_m * 64 + mf * 16;
                float a0f = xs[(rbase + gq)     * XS_STRIDE + k0 + tq];
                float a1f = xs[(rbase + gq + 8) * XS_STRIDE + k0 + tq];
                float a2f = xs[(rbase + gq)     * XS_STRIDE + k0 + tq + 4];
                float a3f = xs[(rbase + gq + 8) * XS_STRIDE + k0 + tq + 4];
                uint32_t a0h, a0l, a1h, a1l, a2h, a2l, a3h, a3l;
                tf32_split(a0f, a0h, a0l); tf32_split(a1f, a1h, a1l);
                tf32_split(a2f, a2h, a2l); tf32_split(a3f, a3h, a3l);
#pragma unroll
                for (int nf = 0; nf < 4; nf++) {
                    mma_tf32(acc[mf][nf], a0h, a1h, a2h, a3h, b0h[nf], b1h[nf]);
                    mma_tf32(acc[mf][nf], a0h, a1h, a2h, a3h, b0l[nf], b1l[nf]);
                    mma_tf32(acc[mf][nf], a0l, a1l, a2l, a3l, b0h[nf], b1h[nf]);
                }
            }
        }
        __syncthreads();
    }

#pragma unroll
    for (int mf = 0; mf < 4; mf++) {
        int rA = row0 + warp_m * 64 + mf * 16 + gq;
        int rB = rA + 8;
        float dvA = (rA < M) ? g_dinv[rA] : 0.f;
        float dvB = (rB < M) ? g_dinv[rB] : 0.f;
#pragma unroll
        for (int nf = 0; nf < 4; nf++) {
            int col = warp_n * 32 + nf * 8 + tq * 2;
            if (rA < M) {
                float2 v = make_float2(acc[mf][nf].x * dvA, acc[mf][nf].y * dvA);
                *(float2*)(g_h + (size_t)rA * OUT_CH + col) = v;
            }
            if (rB < M) {
                float2 v = make_float2(acc[mf][nf].z * dvB, acc[mf][nf].w * dvB);
                *(float2*)(g_h + (size_t)rB * OUT_CH + col) = v;
            }
        }
    }
}

// ---------------------------------------------------------------------------
// Fused gather + epilogue: one warp per node.
// out = minmax+L2norm( dinv[c]*(sum_{src in CSR[c]} g_h[src] + g_h[c]) + b )
// ---------------------------------------------------------------------------
__global__ void __launch_bounds__(256) k_gather_epi(const float* __restrict__ b,
                                                    float* __restrict__ out) {
    int wid  = threadIdx.x >> 5;
    int lane = threadIdx.x & 31;
    int node = blockIdx.x * 8 + wid;
    if (node >= N_NODES) return;

    int s0  = g_off[node];
    int cnt = (int)g_deg[node] - 1;

    // self-loop term (g_h = h*dinv[node])
    float4 sum = ((const float4*)(g_h + (size_t)node * OUT_CH))[lane];

    int i = 0;
    for (; i + 4 <= cnt; i += 4) {
        int s_0 = g_src[s0 + i + 0];
        int s_1 = g_src[s0 + i + 1];
        int s_2 = g_src[s0 + i + 2];
        int s_3 = g_src[s0 + i + 3];
        float4 v0 = ((const float4*)(g_h + (size_t)s_0 * OUT_CH))[lane];
        float4 v1 = ((const float4*)(g_h + (size_t)s_1 * OUT_CH))[lane];
        float4 v2 = ((const float4*)(g_h + (size_t)s_2 * OUT_CH))[lane];
        float4 v3 = ((const float4*)(g_h + (size_t)s_3 * OUT_CH))[lane];
        sum.x += v0.x + v1.x + v2.x + v3.x;
        sum.y += v0.y + v1.y + v2.y + v3.y;
        sum.z += v0.z + v1.z + v2.z + v3.z;
        sum.w += v0.w + v1.w + v2.w + v3.w;
    }
    for (; i < cnt; i++) {
        int s = g_src[s0 + i];
        float4 v = ((const float4*)(g_h + (size_t)s * OUT_CH))[lane];
        sum.x += v.x; sum.y += v.y; sum.z += v.z; sum.w += v.w;
    }

    float sc = g_dinv[node];
    const float4 bv = ((const float4*)b)[lane];
    float4 v;
    v.x = sum.x * sc + bv.x;
    v.y = sum.y * sc + bv.y;
    v.z = sum.z * sc + bv.z;
    v.w = sum.w * sc + bv.w;

    float mn = fminf(fminf(v.x, v.y), fminf(v.z, v.w));
    float mx = fmaxf(fmaxf(v.x, v.y), fmaxf(v.z, v.w));
#pragma unroll
    for (int o = 16; o; o >>= 1) {
        mn = fminf(mn, __shfl_xor_sync(0xffffffffu, mn, o));
        mx = fmaxf(mx, __shfl_xor_sync(0xffffffffu, mx, o));
    }

    float inv = 1.0f / (mx - mn);
    float4 z;
    z.x = (v.x - mn) * inv;
    z.y = (v.y - mn) * inv;
    z.z = (v.z - mn) * inv;
    z.w = (v.w - mn) * inv;

    float ss = z.x * z.x + z.y * z.y + z.z * z.z + z.w * z.w;
#pragma unroll
    for (int o = 16; o; o >>= 1)
        ss += __shfl_xor_sync(0xffffffffu, ss, o);

    float rn = 1.0f / fmaxf(sqrtf(ss), 1e-12f);
    z.x *= rn; z.y *= rn; z.z *= rn; z.w *= rn;

    ((float4*)out)[(size_t)node * 32 + lane] = z;
}

// ---------------------------------------------------------------------------
extern "C" void kernel_launch(void* const* d_in, const int* in_sizes, int n_in,
                              void* d_out, int out_size) {
    const float* x   = (const float*)d_in[0];
    const void*  ei  = d_in[1];
    const float* W   = (const float*)d_in[2];
    const float* b   = (const float*)d_in[3];
    float*       out = (float*)d_out;

    (void)in_sizes; (void)n_in; (void)out_size;

    cudaFuncSetAttribute(k_gemm_mma, cudaFuncAttributeMaxDynamicSharedMemorySize, GSM_BYTES);

    k_detect <<<1, 32>>>((const int*)ei);
    k_deginit<<<NB, 256>>>();
    k_deg    <<<(N_EDGES + 255) / 256, 256>>>(ei);
    k_scan1  <<<NB, 256>>>();
    k_scan2  <<<1, 512>>>();
    k_scan3  <<<NB, 256>>>();
    k_wsplit <<<(IN_CH * OUT_CH + 255) / 256, 256>>>(W);
    k_gemm_mma<<<(N_NODES + 127) / 128, 256, GSM_BYTES>>>(x, N_NODES);
    k_scatter<<<(N_EDGES + 255) / 256, 256>>>(ei);
    k_gather_epi<<<(N_NODES + 7) / 8, 256>>>(b, out);
}

// round 7
// speedup vs baseline: 2.6616x; 1.0988x over previous
#include <cuda_runtime.h>
#include <cstdint>

#define N_NODES 100000
#define N_EDGES 1600000
#define IN_CH   256
#define OUT_CH  128
#define NB      ((N_NODES + 255) / 256)   // 391

// ---------------------------------------------------------------------------
// Scratch (static device globals — allocation-free per harness rules)
// ---------------------------------------------------------------------------
__device__ float g_deg[N_NODES];
__device__ float g_dinv[N_NODES];
__device__ __align__(16) uint32_t g_hb[(size_t)N_NODES * 64];   // h*dinv[row], bf16x2
__device__ __align__(16) float g_Bhi[OUT_CH * IN_CH];           // W^T hi (tf32), [n][k]
__device__ __align__(16) float g_Blo[OUT_CH * IN_CH];           // W^T lo (tf32), [n][k]
__device__ int   g_is64;
__device__ int   g_bsum[NB];
__device__ int   g_boff[NB];
__device__ int   g_off[N_NODES];       // CSR start per destination node
__device__ int   g_cursor[N_NODES];    // scatter cursors (mutable copy)
__device__ int   g_src[N_EDGES];       // CSR source indices

// ---------------------------------------------------------------------------
// helpers
// ---------------------------------------------------------------------------
__device__ __forceinline__ void tf32_split(float v, uint32_t& hi, uint32_t& lo) {
    asm("cvt.rna.tf32.f32 %0, %1;" : "=r"(hi) : "f"(v));
    float r = v - __uint_as_float(hi);
    asm("cvt.rna.tf32.f32 %0, %1;" : "=r"(lo) : "f"(r));
}

__device__ __forceinline__ void mma_tf32(float4& d,
                                         uint32_t a0, uint32_t a1, uint32_t a2, uint32_t a3,
                                         uint32_t b0, uint32_t b1) {
    asm volatile("mma.sync.aligned.m16n8k8.row.col.f32.tf32.tf32.f32 "
                 "{%0,%1,%2,%3}, {%4,%5,%6,%7}, {%8,%9}, {%0,%1,%2,%3};"
                 : "+f"(d.x), "+f"(d.y), "+f"(d.z), "+f"(d.w)
                 : "r"(a0), "r"(a1), "r"(a2), "r"(a3), "r"(b0), "r"(b1));
}

// pack (lo=a, hi=b) into bf16x2 with round-to-nearest
__device__ __forceinline__ uint32_t pack_bf16x2(float a, float b) {
    uint32_t r;
    asm("cvt.rn.bf16x2.f32 %0, %1, %2;" : "=r"(r) : "f"(b), "f"(a));
    return r;
}
// bf16x2 -> two floats (shift/mask, no cvt pipe)
__device__ __forceinline__ float bf_lo(uint32_t p) { return __uint_as_float(p << 16); }
__device__ __forceinline__ float bf_hi(uint32_t p) { return __uint_as_float(p & 0xFFFF0000u); }

// ---------------------------------------------------------------------------
// Detect edge_index dtype + deg init (self loop)
// ---------------------------------------------------------------------------
__global__ void k_detect_init(const int* __restrict__ ei_words) {
    int i = blockIdx.x * blockDim.x + threadIdx.x;
    if (i < N_NODES) g_deg[i] = 1.0f;
    if (i == 0) {
        int all_zero = 1;
        for (int j = 0; j < 64; j++)
            if (ei_words[2 * j + 1] != 0) { all_zero = 0; break; }
        g_is64 = all_zero;
    }
}
__device__ __forceinline__ int edge_idx(const void* ei, int which, int e) {
    if (g_is64) return (int)((const long long*)ei)[(size_t)which * N_EDGES + e];
    return ((const int*)ei)[(size_t)which * N_EDGES + e];
}

__global__ void k_deg(const void* __restrict__ ei) {
    int e = blockIdx.x * blockDim.x + threadIdx.x;
    if (e < N_EDGES) atomicAdd(&g_deg[edge_idx(ei, 1, e)], 1.0f);
}

// ---------------------------------------------------------------------------
// 3-pass exclusive scan of in-degree counts (deg-1) -> g_off, g_cursor; dinv.
// ---------------------------------------------------------------------------
__global__ void k_scan1() {
    __shared__ int sm[256];
    int tid = threadIdx.x;
    int i = blockIdx.x * 256 + tid;
    sm[tid] = (i < N_NODES) ? ((int)g_deg[i] - 1) : 0;
    __syncthreads();
#pragma unroll
    for (int o = 128; o; o >>= 1) {
        if (tid < o) sm[tid] += sm[tid + o];
        __syncthreads();
    }
    if (tid == 0) g_bsum[blockIdx.x] = sm[0];
}

__global__ void k_scan2() {
    __shared__ int sm[512];
    int t = threadIdx.x;
    int v0 = (t < NB) ? g_bsum[t] : 0;
    sm[t] = v0;
    __syncthreads();
#pragma unroll
    for (int o = 1; o < 512; o <<= 1) {
        int v = (t >= o) ? sm[t - o] : 0;
        __syncthreads();
        sm[t] += v;
        __syncthreads();
    }
    if (t < NB) g_boff[t] = sm[t] - v0;   // exclusive
}

__global__ void k_scan3() {
    __shared__ int sm[256];
    int tid = threadIdx.x;
    int i = blockIdx.x * 256 + tid;
    int cnt = (i < N_NODES) ? ((int)g_deg[i] - 1) : 0;
    sm[tid] = cnt;
    __syncthreads();
#pragma unroll
    for (int o = 1; o < 256; o <<= 1) {
        int v = (tid >= o) ? sm[tid - o] : 0;
        __syncthreads();
        sm[tid] += v;
        __syncthreads();
    }
    if (i < N_NODES) {
        int excl = sm[tid] - cnt + g_boff[blockIdx.x];
        g_off[i]    = excl;
        g_cursor[i] = excl;
        g_dinv[i]   = rsqrtf(g_deg[i]);
    }
}

// ---------------------------------------------------------------------------
// Scatter edges into CSR buckets by destination.
// ---------------------------------------------------------------------------
__global__ void k_scatter(const void* __restrict__ ei) {
    int e = blockIdx.x * blockDim.x + threadIdx.x;
    if (e >= N_EDGES) return;
    int c = edge_idx(ei, 1, e);
    int r = edge_idx(ei, 0, e);
    int pos = atomicAdd(&g_cursor[c], 1);
    g_src[pos] = r;
}

// ---------------------------------------------------------------------------
// Transpose + tf32-split W[256][128] -> g_Bhi/g_Blo[n][k]
// ---------------------------------------------------------------------------
__global__ void k_wsplit(const float* __restrict__ W) {
    int g = blockIdx.x * blockDim.x + threadIdx.x;
    if (g >= IN_CH * OUT_CH) return;
    int k = g >> 7;
    int n = g & 127;
    uint32_t hi, lo;
    tf32_split(W[(size_t)k * OUT_CH + n], hi, lo);
    g_Bhi[(size_t)n * IN_CH + k] = __uint_as_float(hi);
    g_Blo[(size_t)n * IN_CH + k] = __uint_as_float(lo);
}

// ---------------------------------------------------------------------------
// Tensor-core GEMM via mma.sync (tf32, 3x split):
//   g_hb[M,64] = bf16x2( (x[M,256] @ W[256,128]) * dinv[row] )
// A split into hi/lo at STAGE time (no redundant per-warp cvt in mainloop).
// ---------------------------------------------------------------------------
#define XS_STRIDE 36
#define GSM_BYTES (4 * 128 * XS_STRIDE * 4)   // xs_hi, xs_lo, wh, wl

__global__ void __launch_bounds__(256, 1) k_gemm_mma(const float* __restrict__ x, int M) {
    extern __shared__ float smem[];
    float* xh = smem;
    float* xl = xh + 128 * XS_STRIDE;
    float* wh = xl + 128 * XS_STRIDE;
    float* wl = wh + 128 * XS_STRIDE;

    const int tid    = threadIdx.x;
    const int wid    = tid >> 5;
    const int lane   = tid & 31;
    const int gq     = lane >> 2;
    const int tq     = lane & 3;
    const int warp_m = wid >> 2;
    const int warp_n = wid & 3;
    const int row0   = blockIdx.x * 128;

    float4 acc[4][4];
#pragma unroll
    for (int i = 0; i < 4; i++)
#pragma unroll
        for (int j = 0; j < 4; j++) acc[i][j] = make_float4(0.f, 0.f, 0.f, 0.f);

    for (int c = 0; c < 8; c++) {
        // stage x chunk split hi/lo: 128 rows x 32 k
#pragma unroll
        for (int i = 0; i < 4; i++) {
            int idx = tid + i * 256;
            int m   = idx >> 3;
            int f4  = idx & 7;
            int gr  = row0 + m;
            float4 v = make_float4(0.f, 0.f, 0.f, 0.f);
            if (gr < M)
                v = *(const float4*)(x + (size_t)gr * IN_CH + c * 32 + f4 * 4);
            uint32_t hx, lx, hy, ly, hz, lz, hw, lw;
            tf32_split(v.x, hx, lx); tf32_split(v.y, hy, ly);
            tf32_split(v.z, hz, lz); tf32_split(v.w, hw, lw);
            *(uint4*)(xh + m * XS_STRIDE + f4 * 4) = make_uint4(hx, hy, hz, hw);
            *(uint4*)(xl + m * XS_STRIDE + f4 * 4) = make_uint4(lx, ly, lz, lw);
        }
        // stage B chunk (pre-split hi/lo)
#pragma unroll
        for (int i = 0; i < 4; i++) {
            int idx = tid + i * 256;
            int n   = idx >> 3;
            int f4  = idx & 7;
            size_t gofs = (size_t)n * IN_CH + c * 32 + f4 * 4;
            *(float4*)(wh + n * XS_STRIDE + f4 * 4) = *(const float4*)(g_Bhi + gofs);
            *(float4*)(wl + n * XS_STRIDE + f4 * 4) = *(const float4*)(g_Blo + gofs);
        }
        __syncthreads();

#pragma unroll
        for (int s = 0; s < 4; s++) {
            const int k0 = s * 8;
            uint32_t b0h[4], b1h[4], b0l[4], b1l[4];
#pragma unroll
            for (int nf = 0; nf < 4; nf++) {
                int n = warp_n * 32 + nf * 8 + gq;
                b0h[nf] = __float_as_uint(wh[n * XS_STRIDE + k0 + tq]);
                b1h[nf] = __float_as_uint(wh[n * XS_STRIDE + k0 + tq + 4]);
                b0l[nf] = __float_as_uint(wl[n * XS_STRIDE + k0 + tq]);
                b1l[nf] = __float_as_uint(wl[n * XS_STRIDE + k0 + tq + 4]);
            }
#pragma unroll
            for (int mf = 0; mf < 4; mf++) {
                int r0 = (warp_m * 64 + mf * 16 + gq) * XS_STRIDE + k0 + tq;
                int r1 = r0 + 8 * XS_STRIDE;
                uint32_t a0h = __float_as_uint(xh[r0]);
                uint32_t a1h = __float_as_uint(xh[r1]);
                uint32_t a2h = __float_as_uint(xh[r0 + 4]);
                uint32_t a3h = __float_as_uint(xh[r1 + 4]);
                uint32_t a0l = __float_as_uint(xl[r0]);
                uint32_t a1l = __float_as_uint(xl[r1]);
                uint32_t a2l = __float_as_uint(xl[r0 + 4]);
                uint32_t a3l = __float_as_uint(xl[r1 + 4]);
#pragma unroll
                for (int nf = 0; nf < 4; nf++) {
                    mma_tf32(acc[mf][nf], a0h, a1h, a2h, a3h, b0h[nf], b1h[nf]);
                    mma_tf32(acc[mf][nf], a0h, a1h, a2h, a3h, b0l[nf], b1l[nf]);
                    mma_tf32(acc[mf][nf], a0l, a1l, a2l, a3l, b0h[nf], b1h[nf]);
                }
            }
        }
        __syncthreads();
    }

    // Store bf16x2: d0,d1 -> (row g, col pair); d2,d3 -> (row g+8)
#pragma unroll
    for (int mf = 0; mf < 4; mf++) {
        int rA = row0 + warp_m * 64 + mf * 16 + gq;
        int rB = rA + 8;
        float dvA = (rA < M) ? g_dinv[rA] : 0.f;
        float dvB = (rB < M) ? g_dinv[rB] : 0.f;
#pragma unroll
        for (int nf = 0; nf < 4; nf++) {
            int cp = warp_n * 16 + nf * 4 + tq;   // u32 (col pair) index
            if (rA < M)
                g_hb[(size_t)rA * 64 + cp] = pack_bf16x2(acc[mf][nf].x * dvA, acc[mf][nf].y * dvA);
            if (rB < M)
                g_hb[(size_t)rB * 64 + cp] = pack_bf16x2(acc[mf][nf].z * dvB, acc[mf][nf].w * dvB);
        }
    }
}

// ---------------------------------------------------------------------------
// Fused gather + epilogue: one warp per node, bf16x2 rows.
// out = minmax+L2norm( dinv[c]*(sum g_hb[src] + g_hb[c]) + b )
// ---------------------------------------------------------------------------
__global__ void __launch_bounds__(256) k_gather_epi(const float* __restrict__ b,
                                                    float* __restrict__ out) {
    int wid  = threadIdx.x >> 5;
    int lane = threadIdx.x & 31;
    int node = blockIdx.x * 8 + wid;
    if (node >= N_NODES) return;

    int s0  = g_off[node];
    int cnt = (int)g_deg[node] - 1;

    // self-loop term
    uint2 sp = ((const uint2*)(g_hb + (size_t)node * 64))[lane];
    float4 sum = make_float4(bf_lo(sp.x), bf_hi(sp.x), bf_lo(sp.y), bf_hi(sp.y));

    int i = 0;
    for (; i + 4 <= cnt; i += 4) {
        int s_0 = g_src[s0 + i + 0];
        int s_1 = g_src[s0 + i + 1];
        int s_2 = g_src[s0 + i + 2];
        int s_3 = g_src[s0 + i + 3];
        uint2 p0 = ((const uint2*)(g_hb + (size_t)s_0 * 64))[lane];
        uint2 p1 = ((const uint2*)(g_hb + (size_t)s_1 * 64))[lane];
        uint2 p2 = ((const uint2*)(g_hb + (size_t)s_2 * 64))[lane];
        uint2 p3 = ((const uint2*)(g_hb + (size_t)s_3 * 64))[lane];
        sum.x += bf_lo(p0.x) + bf_lo(p1.x) + bf_lo(p2.x) + bf_lo(p3.x);
        sum.y += bf_hi(p0.x) + bf_hi(p1.x) + bf_hi(p2.x) + bf_hi(p3.x);
        sum.z += bf_lo(p0.y) + bf_lo(p1.y) + bf_lo(p2.y) + bf_lo(p3.y);
        sum.w += bf_hi(p0.y) + bf_hi(p1.y) + bf_hi(p2.y) + bf_hi(p3.y);
    }
    for (; i < cnt; i++) {
        int s = g_src[s0 + i];
        uint2 p = ((const uint2*)(g_hb + (size_t)s * 64))[lane];
        sum.x += bf_lo(p.x); sum.y += bf_hi(p.x);
        sum.z += bf_lo(p.y); sum.w += bf_hi(p.y);
    }

    float sc = g_dinv[node];
    const float4 bv = ((const float4*)b)[lane];
    float4 v;
    v.x = sum.x * sc + bv.x;
    v.y = sum.y * sc + bv.y;
    v.z = sum.z * sc + bv.z;
    v.w = sum.w * sc + bv.w;

    float mn = fminf(fminf(v.x, v.y), fminf(v.z, v.w));
    float mx = fmaxf(fmaxf(v.x, v.y), fmaxf(v.z, v.w));
#pragma unroll
    for (int o = 16; o; o >>= 1) {
        mn = fminf(mn, __shfl_xor_sync(0xffffffffu, mn, o));
        mx = fmaxf(mx, __shfl_xor_sync(0xffffffffu, mx, o));
    }

    float inv = 1.0f / (mx - mn);
    float4 z;
    z.x = (v.x - mn) * inv;
    z.y = (v.y - mn) * inv;
    z.z = (v.z - mn) * inv;
    z.w = (v.w - mn) * inv;

    float ss = z.x * z.x + z.y * z.y + z.z * z.z + z.w * z.w;
#pragma unroll
    for (int o = 16; o; o >>= 1)
        ss += __shfl_xor_sync(0xffffffffu, ss, o);

    float rn = 1.0f / fmaxf(sqrtf(ss), 1e-12f);
    z.x *= rn; z.y *= rn; z.z *= rn; z.w *= rn;

    ((float4*)out)[(size_t)node * 32 + lane] = z;
}

// ---------------------------------------------------------------------------
extern "C" void kernel_launch(void* const* d_in, const int* in_sizes, int n_in,
                              void* d_out, int out_size) {
    const float* x   = (const float*)d_in[0];
    const void*  ei  = d_in[1];
    const float* W   = (const float*)d_in[2];
    const float* b   = (const float*)d_in[3];
    float*       out = (float*)d_out;

    (void)in_sizes; (void)n_in; (void)out_size;

    cudaFuncSetAttribute(k_gemm_mma, cudaFuncAttributeMaxDynamicSharedMemorySize, GSM_BYTES);

    k_detect_init<<<NB, 256>>>((const int*)ei);
    k_deg    <<<(N_EDGES + 255) / 256, 256>>>(ei);
    k_scan1  <<<NB, 256>>>();
    k_scan2  <<<1, 512>>>();
    k_scan3  <<<NB, 256>>>();
    k_wsplit <<<(IN_CH * OUT_CH + 255) / 256, 256>>>(W);
    k_gemm_mma<<<(N_NODES + 127) / 128, 256, GSM_BYTES>>>(x, N_NODES);
    k_scatter<<<(N_EDGES + 255) / 256, 256>>>(ei);
    k_gather_epi<<<(N_NODES + 7) / 8, 256>>>(b, out);
}

// round 8
// speedup vs baseline: 2.8283x; 1.0626x over previous
#include <cuda_runtime.h>
#include <cstdint>

#define N_NODES 100000
#define N_EDGES 1600000
#define IN_CH   256
#define OUT_CH  128
#define NB      ((N_NODES + 255) / 256)   // 391

// ---------------------------------------------------------------------------
// Scratch (static device globals — allocation-free per harness rules)
// ---------------------------------------------------------------------------
__device__ float g_deg[N_NODES];
__device__ float g_dinv[N_NODES];
__device__ __align__(16) uint32_t g_hb[(size_t)N_NODES * 64];   // h, bf16x2
__device__ __align__(16) float g_Bhi[OUT_CH * IN_CH];           // W^T hi (tf32), [n][k]
__device__ __align__(16) float g_Blo[OUT_CH * IN_CH];           // W^T lo (tf32), [n][k]
__device__ int   g_is64;
__device__ int   g_bsum[NB];
__device__ int   g_boff[NB];
__device__ int   g_off[N_NODES];       // CSR start per destination node
__device__ int   g_cursor[N_NODES];    // scatter cursors (mutable copy)
__device__ int   g_src[N_EDGES];       // CSR source indices

// ---------------------------------------------------------------------------
// helpers
// ---------------------------------------------------------------------------
__device__ __forceinline__ void tf32_split(float v, uint32_t& hi, uint32_t& lo) {
    asm("cvt.rna.tf32.f32 %0, %1;" : "=r"(hi) : "f"(v));
    float r = v - __uint_as_float(hi);
    asm("cvt.rna.tf32.f32 %0, %1;" : "=r"(lo) : "f"(r));
}

__device__ __forceinline__ void mma_tf32(float4& d,
                                         uint32_t a0, uint32_t a1, uint32_t a2, uint32_t a3,
                                         uint32_t b0, uint32_t b1) {
    asm volatile("mma.sync.aligned.m16n8k8.row.col.f32.tf32.tf32.f32 "
                 "{%0,%1,%2,%3}, {%4,%5,%6,%7}, {%8,%9}, {%0,%1,%2,%3};"
                 : "+f"(d.x), "+f"(d.y), "+f"(d.z), "+f"(d.w)
                 : "r"(a0), "r"(a1), "r"(a2), "r"(a3), "r"(b0), "r"(b1));
}

__device__ __forceinline__ uint32_t pack_bf16x2(float a, float b) {
    uint32_t r;
    asm("cvt.rn.bf16x2.f32 %0, %1, %2;" : "=r"(r) : "f"(b), "f"(a));
    return r;
}
__device__ __forceinline__ float bf_lo(uint32_t p) { return __uint_as_float(p << 16); }
__device__ __forceinline__ float bf_hi(uint32_t p) { return __uint_as_float(p & 0xFFFF0000u); }

// ---------------------------------------------------------------------------
// Transpose + tf32-split W[256][128] -> g_Bhi/g_Blo[n][k]   (launch #1)
// ---------------------------------------------------------------------------
__global__ void k_wsplit(const float* __restrict__ W) {
    int g = blockIdx.x * blockDim.x + threadIdx.x;
    if (g >= IN_CH * OUT_CH) return;
    int k = g >> 7;
    int n = g & 127;
    uint32_t hi, lo;
    tf32_split(W[(size_t)k * OUT_CH + n], hi, lo);
    g_Bhi[(size_t)n * IN_CH + k] = __uint_as_float(hi);
    g_Blo[(size_t)n * IN_CH + k] = __uint_as_float(lo);
}

// ---------------------------------------------------------------------------
// Detect edge_index dtype + deg init (self loop)    (launch #2)
// ---------------------------------------------------------------------------
__global__ void k_detect_init(const int* __restrict__ ei_words) {
    int i = blockIdx.x * blockDim.x + threadIdx.x;
    if (i < N_NODES) g_deg[i] = 1.0f;
    if (i == 0) {
        int all_zero = 1;
        for (int j = 0; j < 64; j++)
            if (ei_words[2 * j + 1] != 0) { all_zero = 0; break; }
        g_is64 = all_zero;
    }
}
__device__ __forceinline__ int edge_idx(const void* ei, int which, int e) {
    if (g_is64) return (int)((const long long*)ei)[(size_t)which * N_EDGES + e];
    return ((const int*)ei)[(size_t)which * N_EDGES + e];
}

__global__ void k_deg(const void* __restrict__ ei) {    // launch #3
    int e = blockIdx.x * blockDim.x + threadIdx.x;
    if (e < N_EDGES) atomicAdd(&g_deg[edge_idx(ei, 1, e)], 1.0f);
}

// ---------------------------------------------------------------------------
// Tensor-core GEMM via mma.sync (tf32, 3x split):  g_hb = bf16x2(x @ W)
// K-chunk 64 (4 chunks), A split hi/lo at stage time.      (launch #4 — profiled)
// ---------------------------------------------------------------------------
#define XS_STRIDE 68
#define GSM_BYTES (4 * 128 * XS_STRIDE * 4)   // xh, xl, wh, wl = 139264

__global__ void __launch_bounds__(256, 1) k_gemm_mma(const float* __restrict__ x, int M) {
    extern __shared__ float smem[];
    float* xh = smem;
    float* xl = xh + 128 * XS_STRIDE;
    float* wh = xl + 128 * XS_STRIDE;
    float* wl = wh + 128 * XS_STRIDE;

    const int tid    = threadIdx.x;
    const int wid    = tid >> 5;
    const int lane   = tid & 31;
    const int gq     = lane >> 2;
    const int tq     = lane & 3;
    const int warp_m = wid >> 2;
    const int warp_n = wid & 3;
    const int row0   = blockIdx.x * 128;

    float4 acc[4][4];
#pragma unroll
    for (int i = 0; i < 4; i++)
#pragma unroll
        for (int j = 0; j < 4; j++) acc[i][j] = make_float4(0.f, 0.f, 0.f, 0.f);

    // thread -> (row, f4) staging map: 16 f4 per 128-row x 64-k chunk per 2048B...
    // per chunk: 128 rows x 16 float4 = 2048 f4; 8 per thread.
    for (int c = 0; c < 4; c++) {
#pragma unroll
        for (int i = 0; i < 8; i++) {
            int idx = tid + i * 256;          // 0..2047
            int m   = idx >> 4;               // 0..127
            int f4  = idx & 15;               // 0..15
            int gr  = row0 + m;
            float4 v = make_float4(0.f, 0.f, 0.f, 0.f);
            if (gr < M)
                v = *(const float4*)(x + (size_t)gr * IN_CH + c * 64 + f4 * 4);
            uint32_t hx, lx, hy, ly, hz, lz, hw, lw;
            tf32_split(v.x, hx, lx); tf32_split(v.y, hy, ly);
            tf32_split(v.z, hz, lz); tf32_split(v.w, hw, lw);
            *(uint4*)(xh + m * XS_STRIDE + f4 * 4) = make_uint4(hx, hy, hz, hw);
            *(uint4*)(xl + m * XS_STRIDE + f4 * 4) = make_uint4(lx, ly, lz, lw);
        }
#pragma unroll
        for (int i = 0; i < 8; i++) {
            int idx = tid + i * 256;
            int n   = idx >> 4;
            int f4  = idx & 15;
            size_t gofs = (size_t)n * IN_CH + c * 64 + f4 * 4;
            *(float4*)(wh + n * XS_STRIDE + f4 * 4) = *(const float4*)(g_Bhi + gofs);
            *(float4*)(wl + n * XS_STRIDE + f4 * 4) = *(const float4*)(g_Blo + gofs);
        }
        __syncthreads();

#pragma unroll
        for (int s = 0; s < 8; s++) {
            const int k0 = s * 8;
            uint32_t b0h[4], b1h[4], b0l[4], b1l[4];
#pragma unroll
            for (int nf = 0; nf < 4; nf++) {
                int n = warp_n * 32 + nf * 8 + gq;
                b0h[nf] = __float_as_uint(wh[n * XS_STRIDE + k0 + tq]);
                b1h[nf] = __float_as_uint(wh[n * XS_STRIDE + k0 + tq + 4]);
                b0l[nf] = __float_as_uint(wl[n * XS_STRIDE + k0 + tq]);
                b1l[nf] = __float_as_uint(wl[n * XS_STRIDE + k0 + tq + 4]);
            }
#pragma unroll
            for (int mf = 0; mf < 4; mf++) {
                int r0 = (warp_m * 64 + mf * 16 + gq) * XS_STRIDE + k0 + tq;
                int r1 = r0 + 8 * XS_STRIDE;
                uint32_t a0h = __float_as_uint(xh[r0]);
                uint32_t a1h = __float_as_uint(xh[r1]);
                uint32_t a2h = __float_as_uint(xh[r0 + 4]);
                uint32_t a3h = __float_as_uint(xh[r1 + 4]);
                uint32_t a0l = __float_as_uint(xl[r0]);
                uint32_t a1l = __float_as_uint(xl[r1]);
                uint32_t a2l = __float_as_uint(xl[r0 + 4]);
                uint32_t a3l = __float_as_uint(xl[r1 + 4]);
#pragma unroll
                for (int nf = 0; nf < 4; nf++) {
                    mma_tf32(acc[mf][nf], a0h, a1h, a2h, a3h, b0h[nf], b1h[nf]);
                    mma_tf32(acc[mf][nf], a0h, a1h, a2h, a3h, b0l[nf], b1l[nf]);
                    mma_tf32(acc[mf][nf], a0l, a1l, a2l, a3l, b0h[nf], b1h[nf]);
                }
            }
        }
        __syncthreads();
    }

    // Store bf16x2(h) — dinv applied in gather.
#pragma unroll
    for (int mf = 0; mf < 4; mf++) {
        int rA = row0 + warp_m * 64 + mf * 16 + gq;
        int rB = rA + 8;
#pragma unroll
        for (int nf = 0; nf < 4; nf++) {
            int cp = warp_n * 16 + nf * 4 + tq;
            if (rA < M)
                g_hb[(size_t)rA * 64 + cp] = pack_bf16x2(acc[mf][nf].x, acc[mf][nf].y);
            if (rB < M)
                g_hb[(size_t)rB * 64 + cp] = pack_bf16x2(acc[mf][nf].z, acc[mf][nf].w);
        }
    }
}

// ---------------------------------------------------------------------------
// 3-pass exclusive scan of in-degree counts (deg-1) -> g_off, g_cursor; dinv.
// ---------------------------------------------------------------------------
__global__ void k_scan1() {
    __shared__ int sm[256];
    int tid = threadIdx.x;
    int i = blockIdx.x * 256 + tid;
    sm[tid] = (i < N_NODES) ? ((int)g_deg[i] - 1) : 0;
    __syncthreads();
#pragma unroll
    for (int o = 128; o; o >>= 1) {
        if (tid < o) sm[tid] += sm[tid + o];
        __syncthreads();
    }
    if (tid == 0) g_bsum[blockIdx.x] = sm[0];
}

__global__ void k_scan2() {
    __shared__ int sm[512];
    int t = threadIdx.x;
    int v0 = (t < NB) ? g_bsum[t] : 0;
    sm[t] = v0;
    __syncthreads();
#pragma unroll
    for (int o = 1; o < 512; o <<= 1) {
        int v = (t >= o) ? sm[t - o] : 0;
        __syncthreads();
        sm[t] += v;
        __syncthreads();
    }
    if (t < NB) g_boff[t] = sm[t] - v0;   // exclusive
}

__global__ void k_scan3() {
    __shared__ int sm[256];
    int tid = threadIdx.x;
    int i = blockIdx.x * 256 + tid;
    int cnt = (i < N_NODES) ? ((int)g_deg[i] - 1) : 0;
    sm[tid] = cnt;
    __syncthreads();
#pragma unroll
    for (int o = 1; o < 256; o <<= 1) {
        int v = (tid >= o) ? sm[tid - o] : 0;
        __syncthreads();
        sm[tid] += v;
        __syncthreads();
    }
    if (i < N_NODES) {
        int excl = sm[tid] - cnt + g_boff[blockIdx.x];
        g_off[i]    = excl;
        g_cursor[i] = excl;
        g_dinv[i]   = rsqrtf(g_deg[i]);
    }
}

// ---------------------------------------------------------------------------
// Scatter edges into CSR buckets by destination.
// ---------------------------------------------------------------------------
__global__ void k_scatter(const void* __restrict__ ei) {
    int e = blockIdx.x * blockDim.x + threadIdx.x;
    if (e >= N_EDGES) return;
    int c = edge_idx(ei, 1, e);
    int r = edge_idx(ei, 0, e);
    int pos = atomicAdd(&g_cursor[c], 1);
    g_src[pos] = r;
}

// ---------------------------------------------------------------------------
// Fused gather + epilogue: one warp per node, bf16x2 rows, 8-deep prefetch.
// out = minmax+L2norm( dinv[c]*(sum dinv[s]*h[s] + dinv[c]*h[c]) + b )
// ---------------------------------------------------------------------------
__global__ void __launch_bounds__(256) k_gather_epi(const float* __restrict__ b,
                                                    float* __restrict__ out) {
    int wid  = threadIdx.x >> 5;
    int lane = threadIdx.x & 31;
    int node = blockIdx.x * 8 + wid;
    if (node >= N_NODES) return;

    int s0  = g_off[node];
    int cnt = (int)g_deg[node] - 1;
    float dvc = g_dinv[node];

    // self-loop term: dinv[node] * h[node]
    uint2 sp = ((const uint2*)(g_hb + (size_t)node * 64))[lane];
    float4 sum = make_float4(bf_lo(sp.x) * dvc, bf_hi(sp.x) * dvc,
                             bf_lo(sp.y) * dvc, bf_hi(sp.y) * dvc);

    int i = 0;
    for (; i + 8 <= cnt; i += 8) {
        int   si[8];
        float dv[8];
        uint2 p[8];
#pragma unroll
        for (int j = 0; j < 8; j++) si[j] = __ldg(&g_src[s0 + i + j]);
#pragma unroll
        for (int j = 0; j < 8; j++) dv[j] = __ldg(&g_dinv[si[j]]);
#pragma unroll
        for (int j = 0; j < 8; j++)
            p[j] = __ldg(&((const uint2*)(g_hb + (size_t)si[j] * 64))[lane]);
#pragma unroll
        for (int j = 0; j < 8; j++) {
            sum.x += bf_lo(p[j].x) * dv[j];
            sum.y += bf_hi(p[j].x) * dv[j];
            sum.z += bf_lo(p[j].y) * dv[j];
            sum.w += bf_hi(p[j].y) * dv[j];
        }
    }
    for (; i < cnt; i++) {
        int s = __ldg(&g_src[s0 + i]);
        float dv = __ldg(&g_dinv[s]);
        uint2 p = __ldg(&((const uint2*)(g_hb + (size_t)s * 64))[lane]);
        sum.x += bf_lo(p.x) * dv; sum.y += bf_hi(p.x) * dv;
        sum.z += bf_lo(p.y) * dv; sum.w += bf_hi(p.y) * dv;
    }

    const float4 bv = ((const float4*)b)[lane];
    float4 v;
    v.x = sum.x * dvc + bv.x;
    v.y = sum.y * dvc + bv.y;
    v.z = sum.z * dvc + bv.z;
    v.w = sum.w * dvc + bv.w;

    float mn = fminf(fminf(v.x, v.y), fminf(v.z, v.w));
    float mx = fmaxf(fmaxf(v.x, v.y), fmaxf(v.z, v.w));
#pragma unroll
    for (int o = 16; o; o >>= 1) {
        mn = fminf(mn, __shfl_xor_sync(0xffffffffu, mn, o));
        mx = fmaxf(mx, __shfl_xor_sync(0xffffffffu, mx, o));
    }

    float inv = 1.0f / (mx - mn);
    float4 z;
    z.x = (v.x - mn) * inv;
    z.y = (v.y - mn) * inv;
    z.z = (v.z - mn) * inv;
    z.w = (v.w - mn) * inv;

    float ss = z.x * z.x + z.y * z.y + z.z * z.z + z.w * z.w;
#pragma unroll
    for (int o = 16; o; o >>= 1)
        ss += __shfl_xor_sync(0xffffffffu, ss, o);

    float rn = 1.0f / fmaxf(sqrtf(ss), 1e-12f);
    z.x *= rn; z.y *= rn; z.z *= rn; z.w *= rn;

    ((float4*)out)[(size_t)node * 32 + lane] = z;
}

// ---------------------------------------------------------------------------
extern "C" void kernel_launch(void* const* d_in, const int* in_sizes, int n_in,
                              void* d_out, int out_size) {
    const float* x   = (const float*)d_in[0];
    const void*  ei  = d_in[1];
    const float* W   = (const float*)d_in[2];
    const float* b   = (const float*)d_in[3];
    float*       out = (float*)d_out;

    (void)in_sizes; (void)n_in; (void)out_size;

    cudaFuncSetAttribute(k_gemm_mma, cudaFuncAttributeMaxDynamicSharedMemorySize, GSM_BYTES);

    k_wsplit     <<<(IN_CH * OUT_CH + 255) / 256, 256>>>(W);   // 1
    k_detect_init<<<NB, 256>>>((const int*)ei);                // 2
    k_deg        <<<(N_EDGES + 255) / 256, 256>>>(ei);         // 3
    k_gemm_mma   <<<(N_NODES + 127) / 128, 256, GSM_BYTES>>>(x, N_NODES);  // 4 (profiled)
    k_scan1      <<<NB, 256>>>();                              // 5
    k_scan2      <<<1, 512>>>();                               // 6
    k_scan3      <<<NB, 256>>>();                              // 7
    k_scatter    <<<(N_EDGES + 255) / 256, 256>>>(ei);         // 8
    k_gather_epi <<<(N_NODES + 7) / 8, 256>>>(b, out);         // 9
}

// round 9
// speedup vs baseline: 3.8784x; 1.3713x over previous
#include <cuda_runtime.h>
#include <cstdint>

#define N_NODES 100000
#define N_EDGES 1600000
#define IN_CH   256
#define OUT_CH  128
#define NB      ((N_NODES + 255) / 256)   // 391

// ---------------------------------------------------------------------------
// Scratch (static device globals — allocation-free per harness rules)
// ---------------------------------------------------------------------------
__device__ float g_deg[N_NODES];
__device__ float g_dinv[N_NODES];
__device__ __align__(16) uint32_t g_hb[(size_t)N_NODES * 64];   // h, bf16x2
__device__ __align__(16) uint32_t g_Bh[OUT_CH * 128];           // W^T hi bf16x2 [n][kpair]
__device__ __align__(16) uint32_t g_Bl[OUT_CH * 128];           // W^T lo bf16x2 [n][kpair]
__device__ int   g_is64;
__device__ int   g_bsum[NB];
__device__ int   g_boff[NB];
__device__ int   g_off[N_NODES];       // CSR start per destination node
__device__ int   g_cursor[N_NODES];    // scatter cursors (mutable copy)
__device__ int   g_src[N_EDGES];       // CSR source indices

// ---------------------------------------------------------------------------
// helpers
// ---------------------------------------------------------------------------
__device__ __forceinline__ float trunc_bf16(float v) {
    return __uint_as_float(__float_as_uint(v) & 0xFFFF0000u);
}
__device__ __forceinline__ uint32_t pack_bf16x2(float a, float b) {
    uint32_t r;
    asm("cvt.rn.bf16x2.f32 %0, %1, %2;" : "=r"(r) : "f"(b), "f"(a));
    return r;
}
__device__ __forceinline__ float bf_lo(uint32_t p) { return __uint_as_float(p << 16); }
__device__ __forceinline__ float bf_hi(uint32_t p) { return __uint_as_float(p & 0xFFFF0000u); }

// bf16 m16n8k16 mma: D += A*B (fp32 accumulate)
__device__ __forceinline__ void mma_bf16(float4& d,
                                         uint32_t a0, uint32_t a1, uint32_t a2, uint32_t a3,
                                         uint32_t b0, uint32_t b1) {
    asm volatile("mma.sync.aligned.m16n8k16.row.col.f32.bf16.bf16.f32 "
                 "{%0,%1,%2,%3}, {%4,%5,%6,%7}, {%8,%9}, {%0,%1,%2,%3};"
                 : "+f"(d.x), "+f"(d.y), "+f"(d.z), "+f"(d.w)
                 : "r"(a0), "r"(a1), "r"(a2), "r"(a3), "r"(b0), "r"(b1));
}

// ---------------------------------------------------------------------------
// Transpose + bf16-split W[256][128] -> g_Bh/g_Bl packed pairs   (launch #1)
// ---------------------------------------------------------------------------
__global__ void k_wsplit(const float* __restrict__ W) {
    int g = blockIdx.x * blockDim.x + threadIdx.x;   // 16384
    if (g >= OUT_CH * 128) return;
    int n  = g >> 7;
    int kp = g & 127;                                // k pair index
    float v0 = W[(size_t)(2 * kp)     * OUT_CH + n];
    float v1 = W[(size_t)(2 * kp + 1) * OUT_CH + n];
    float h0 = trunc_bf16(v0), h1 = trunc_bf16(v1);
    g_Bh[(size_t)n * 128 + kp] = pack_bf16x2(h0, h1);
    g_Bl[(size_t)n * 128 + kp] = pack_bf16x2(v0 - h0, v1 - h1);
}

// ---------------------------------------------------------------------------
// Detect edge_index dtype + deg init (self loop)    (launch #2)
// ---------------------------------------------------------------------------
__global__ void k_detect_init(const int* __restrict__ ei_words) {
    int i = blockIdx.x * blockDim.x + threadIdx.x;
    if (i < N_NODES) g_deg[i] = 1.0f;
    if (i == 0) {
        int all_zero = 1;
        for (int j = 0; j < 64; j++)
            if (ei_words[2 * j + 1] != 0) { all_zero = 0; break; }
        g_is64 = all_zero;
    }
}
__device__ __forceinline__ int edge_idx(const void* ei, int which, int e) {
    if (g_is64) return (int)((const long long*)ei)[(size_t)which * N_EDGES + e];
    return ((const int*)ei)[(size_t)which * N_EDGES + e];
}

__global__ void k_deg(const void* __restrict__ ei) {    // launch #3
    int e = blockIdx.x * blockDim.x + threadIdx.x;
    if (e < N_EDGES) atomicAdd(&g_deg[edge_idx(ei, 1, e)], 1.0f);
}

// ---------------------------------------------------------------------------
// bf16 3x-split GEMM via mma.sync m16n8k16:  g_hb = bf16x2(x @ W)
// CTA tile 128x128, K-chunk 64 (32 pairs), smem 73.7KB -> 2 CTAs/SM.
// (launch #4 — profiled)
// ---------------------------------------------------------------------------
#define XS_STRIDE 36                      // u32 pairs per row (32 data + 4 pad)
#define GSM_BYTES (4 * 128 * XS_STRIDE * 4)   // xh, xl, wh, wl = 73728

__global__ void __launch_bounds__(256, 2) k_gemm_mma(const float* __restrict__ x, int M) {
    extern __shared__ uint32_t smem_u[];
    uint32_t* xh = smem_u;
    uint32_t* xl = xh + 128 * XS_STRIDE;
    uint32_t* wh = xl + 128 * XS_STRIDE;
    uint32_t* wl = wh + 128 * XS_STRIDE;

    const int tid    = threadIdx.x;
    const int wid    = tid >> 5;
    const int lane   = tid & 31;
    const int gq     = lane >> 2;
    const int tq     = lane & 3;
    const int warp_m = wid >> 2;
    const int warp_n = wid & 3;
    const int row0   = blockIdx.x * 128;

    float4 acc[4][4];
#pragma unroll
    for (int i = 0; i < 4; i++)
#pragma unroll
        for (int j = 0; j < 4; j++) acc[i][j] = make_float4(0.f, 0.f, 0.f, 0.f);

    for (int c = 0; c < 4; c++) {
        // stage x chunk: 128 rows x 64 k = 128 x 16 float4; 8 per thread.
#pragma unroll
        for (int i = 0; i < 8; i++) {
            int idx = tid + i * 256;          // 0..2047
            int m   = idx >> 4;               // 0..127
            int f4  = idx & 15;               // 0..15 (two k-pairs each)
            int gr  = row0 + m;
            float4 v = make_float4(0.f, 0.f, 0.f, 0.f);
            if (gr < M)
                v = *(const float4*)(x + (size_t)gr * IN_CH + c * 64 + f4 * 4);
            float h0 = trunc_bf16(v.x), h1 = trunc_bf16(v.y);
            float h2 = trunc_bf16(v.z), h3 = trunc_bf16(v.w);
            uint2 ph = make_uint2(pack_bf16x2(h0, h1), pack_bf16x2(h2, h3));
            uint2 pl = make_uint2(pack_bf16x2(v.x - h0, v.y - h1),
                                  pack_bf16x2(v.z - h2, v.w - h3));
            *(uint2*)(xh + m * XS_STRIDE + f4 * 2) = ph;
            *(uint2*)(xl + m * XS_STRIDE + f4 * 2) = pl;
        }
        // stage W chunk (pre-split pairs): 128 n x 32 pairs = 128 x 8 uint4; 4/thread
#pragma unroll
        for (int i = 0; i < 4; i++) {
            int idx = tid + i * 256;          // 0..1023
            int n   = idx >> 3;               // 0..127
            int f4  = idx & 7;                // 0..7
            size_t gofs = (size_t)n * 128 + c * 32 + f4 * 4;
            *(uint4*)(wh + n * XS_STRIDE + f4 * 4) = *(const uint4*)(g_Bh + gofs);
            *(uint4*)(wl + n * XS_STRIDE + f4 * 4) = *(const uint4*)(g_Bl + gofs);
        }
        __syncthreads();

#pragma unroll
        for (int s = 0; s < 4; s++) {         // K=16 per step -> pair base 8s
            const int p0 = s * 8;
            uint32_t b0h[4], b1h[4], b0l[4], b1l[4];
#pragma unroll
            for (int nf = 0; nf < 4; nf++) {
                int n = warp_n * 32 + nf * 8 + gq;
                b0h[nf] = wh[n * XS_STRIDE + p0 + tq];
                b1h[nf] = wh[n * XS_STRIDE + p0 + tq + 4];
                b0l[nf] = wl[n * XS_STRIDE + p0 + tq];
                b1l[nf] = wl[n * XS_STRIDE + p0 + tq + 4];
            }
#pragma unroll
            for (int mf = 0; mf < 4; mf++) {
                int r0 = (warp_m * 64 + mf * 16 + gq) * XS_STRIDE + p0 + tq;
                int r1 = r0 + 8 * XS_STRIDE;
                uint32_t a0h = xh[r0], a1h = xh[r1], a2h = xh[r0 + 4], a3h = xh[r1 + 4];
                uint32_t a0l = xl[r0], a1l = xl[r1], a2l = xl[r0 + 4], a3l = xl[r1 + 4];
#pragma unroll
                for (int nf = 0; nf < 4; nf++) {
                    mma_bf16(acc[mf][nf], a0h, a1h, a2h, a3h, b0h[nf], b1h[nf]);
                    mma_bf16(acc[mf][nf], a0h, a1h, a2h, a3h, b0l[nf], b1l[nf]);
                    mma_bf16(acc[mf][nf], a0l, a1l, a2l, a3l, b0h[nf], b1h[nf]);
                }
            }
        }
        __syncthreads();
    }

    // Store bf16x2(h) — dinv applied in gather.
#pragma unroll
    for (int mf = 0; mf < 4; mf++) {
        int rA = row0 + warp_m * 64 + mf * 16 + gq;
        int rB = rA + 8;
#pragma unroll
        for (int nf = 0; nf < 4; nf++) {
            int cp = warp_n * 16 + nf * 4 + tq;
            if (rA < M)
                g_hb[(size_t)rA * 64 + cp] = pack_bf16x2(acc[mf][nf].x, acc[mf][nf].y);
            if (rB < M)
                g_hb[(size_t)rB * 64 + cp] = pack_bf16x2(acc[mf][nf].z, acc[mf][nf].w);
        }
    }
}

// ---------------------------------------------------------------------------
// 3-pass exclusive scan of in-degree counts (deg-1) -> g_off, g_cursor; dinv.
// ---------------------------------------------------------------------------
__global__ void k_scan1() {
    __shared__ int sm[256];
    int tid = threadIdx.x;
    int i = blockIdx.x * 256 + tid;
    sm[tid] = (i < N_NODES) ? ((int)g_deg[i] - 1) : 0;
    __syncthreads();
#pragma unroll
    for (int o = 128; o; o >>= 1) {
        if (tid < o) sm[tid] += sm[tid + o];
        __syncthreads();
    }
    if (tid == 0) g_bsum[blockIdx.x] = sm[0];
}

__global__ void k_scan2() {
    __shared__ int sm[512];
    int t = threadIdx.x;
    int v0 = (t < NB) ? g_bsum[t] : 0;
    sm[t] = v0;
    __syncthreads();
#pragma unroll
    for (int o = 1; o < 512; o <<= 1) {
        int v = (t >= o) ? sm[t - o] : 0;
        __syncthreads();
        sm[t] += v;
        __syncthreads();
    }
    if (t < NB) g_boff[t] = sm[t] - v0;   // exclusive
}

__global__ void k_scan3() {
    __shared__ int sm[256];
    int tid = threadIdx.x;
    int i = blockIdx.x * 256 + tid;
    int cnt = (i < N_NODES) ? ((int)g_deg[i] - 1) : 0;
    sm[tid] = cnt;
    __syncthreads();
#pragma unroll
    for (int o = 1; o < 256; o <<= 1) {
        int v = (tid >= o) ? sm[tid - o] : 0;
        __syncthreads();
        sm[tid] += v;
        __syncthreads();
    }
    if (i < N_NODES) {
        int excl = sm[tid] - cnt + g_boff[blockIdx.x];
        g_off[i]    = excl;
        g_cursor[i] = excl;
        g_dinv[i]   = rsqrtf(g_deg[i]);
    }
}

// ---------------------------------------------------------------------------
// Scatter edges into CSR buckets by destination.
// ---------------------------------------------------------------------------
__global__ void k_scatter(const void* __restrict__ ei) {
    int e = blockIdx.x * blockDim.x + threadIdx.x;
    if (e >= N_EDGES) return;
    int c = edge_idx(ei, 1, e);
    int r = edge_idx(ei, 0, e);
    int pos = atomicAdd(&g_cursor[c], 1);
    g_src[pos] = r;
}

// ---------------------------------------------------------------------------
// Fused gather + epilogue: one warp per node, bf16x2 rows, 8-deep prefetch.
// ---------------------------------------------------------------------------
__global__ void __launch_bounds__(256) k_gather_epi(const float* __restrict__ b,
                                                    float* __restrict__ out) {
    int wid  = threadIdx.x >> 5;
    int lane = threadIdx.x & 31;
    int node = blockIdx.x * 8 + wid;
    if (node >= N_NODES) return;

    int s0  = g_off[node];
    int cnt = (int)g_deg[node] - 1;
    float dvc = g_dinv[node];

    uint2 sp = ((const uint2*)(g_hb + (size_t)node * 64))[lane];
    float4 sum = make_float4(bf_lo(sp.x) * dvc, bf_hi(sp.x) * dvc,
                             bf_lo(sp.y) * dvc, bf_hi(sp.y) * dvc);

    int i = 0;
    for (; i + 8 <= cnt; i += 8) {
        int   si[8];
        float dv[8];
        uint2 p[8];
#pragma unroll
        for (int j = 0; j < 8; j++) si[j] = __ldg(&g_src[s0 + i + j]);
#pragma unroll
        for (int j = 0; j < 8; j++) dv[j] = __ldg(&g_dinv[si[j]]);
#pragma unroll
        for (int j = 0; j < 8; j++)
            p[j] = __ldg(&((const uint2*)(g_hb + (size_t)si[j] * 64))[lane]);
#pragma unroll
        for (int j = 0; j < 8; j++) {
            sum.x += bf_lo(p[j].x) * dv[j];
            sum.y += bf_hi(p[j].x) * dv[j];
            sum.z += bf_lo(p[j].y) * dv[j];
            sum.w += bf_hi(p[j].y) * dv[j];
        }
    }
    for (; i < cnt; i++) {
        int s = __ldg(&g_src[s0 + i]);
        float dv = __ldg(&g_dinv[s]);
        uint2 p = __ldg(&((const uint2*)(g_hb + (size_t)s * 64))[lane]);
        sum.x += bf_lo(p.x) * dv; sum.y += bf_hi(p.x) * dv;
        sum.z += bf_lo(p.y) * dv; sum.w += bf_hi(p.y) * dv;
    }

    const float4 bv = ((const float4*)b)[lane];
    float4 v;
    v.x = sum.x * dvc + bv.x;
    v.y = sum.y * dvc + bv.y;
    v.z = sum.z * dvc + bv.z;
    v.w = sum.w * dvc + bv.w;

    float mn = fminf(fminf(v.x, v.y), fminf(v.z, v.w));
    float mx = fmaxf(fmaxf(v.x, v.y), fmaxf(v.z, v.w));
#pragma unroll
    for (int o = 16; o; o >>= 1) {
        mn = fminf(mn, __shfl_xor_sync(0xffffffffu, mn, o));
        mx = fmaxf(mx, __shfl_xor_sync(0xffffffffu, mx, o));
    }

    float inv = 1.0f / (mx - mn);
    float4 z;
    z.x = (v.x - mn) * inv;
    z.y = (v.y - mn) * inv;
    z.z = (v.z - mn) * inv;
    z.w = (v.w - mn) * inv;

    float ss = z.x * z.x + z.y * z.y + z.z * z.z + z.w * z.w;
#pragma unroll
    for (int o = 16; o; o >>= 1)
        ss += __shfl_xor_sync(0xffffffffu, ss, o);

    float rn = 1.0f / fmaxf(sqrtf(ss), 1e-12f);
    z.x *= rn; z.y *= rn; z.z *= rn; z.w *= rn;

    ((float4*)out)[(size_t)node * 32 + lane] = z;
}

// ---------------------------------------------------------------------------
extern "C" void kernel_launch(void* const* d_in, const int* in_sizes, int n_in,
                              void* d_out, int out_size) {
    const float* x   = (const float*)d_in[0];
    const void*  ei  = d_in[1];
    const float* W   = (const float*)d_in[2];
    const float* b   = (const float*)d_in[3];
    float*       out = (float*)d_out;

    (void)in_sizes; (void)n_in; (void)out_size;

    cudaFuncSetAttribute(k_gemm_mma, cudaFuncAttributeMaxDynamicSharedMemorySize, GSM_BYTES);

    k_wsplit     <<<(OUT_CH * 128 + 255) / 256, 256>>>(W);     // 1
    k_detect_init<<<NB, 256>>>((const int*)ei);                // 2
    k_deg        <<<(N_EDGES + 255) / 256, 256>>>(ei);         // 3
    k_gemm_mma   <<<(N_NODES + 127) / 128, 256, GSM_BYTES>>>(x, N_NODES);  // 4 (profiled)
    k_scan1      <<<NB, 256>>>();                              // 5
    k_scan2      <<<1, 512>>>();                               // 6
    k_scan3      <<<NB, 256>>>();                              // 7
    k_scatter    <<<(N_EDGES + 255) / 256, 256>>>(ei);         // 8
    k_gather_epi <<<(N_NODES + 7) / 8, 256>>>(b, out);         // 9
}

// round 10
// speedup vs baseline: 4.1183x; 1.0619x over previous
#include <cuda_runtime.h>
#include <cstdint>

#define N_NODES 100000
#define N_EDGES 1600000
#define IN_CH   256
#define OUT_CH  128
#define NB      ((N_NODES + 255) / 256)   // 391

// ---------------------------------------------------------------------------
// Scratch (static device globals — allocation-free per harness rules)
// ---------------------------------------------------------------------------
__device__ float g_deg[N_NODES];
__device__ float g_dinv[N_NODES];
__device__ __align__(16) uint32_t g_hb[(size_t)N_NODES * 64];   // h, bf16x2
__device__ __align__(16) uint32_t g_Bh[OUT_CH * 128];           // W^T hi bf16x2 [n][kpair]
__device__ __align__(16) uint32_t g_Bl[OUT_CH * 128];           // W^T lo bf16x2 [n][kpair]
__device__ int   g_is64;
__device__ int   g_bsum[NB];
__device__ int   g_boff[NB];
__device__ int   g_off[N_NODES];
__device__ int   g_cursor[N_NODES];
__device__ int   g_src[N_EDGES];

// ---------------------------------------------------------------------------
// helpers
// ---------------------------------------------------------------------------
__device__ __forceinline__ float trunc_bf16(float v) {
    return __uint_as_float(__float_as_uint(v) & 0xFFFF0000u);
}
__device__ __forceinline__ uint32_t pack_bf16x2(float a, float b) {
    uint32_t r;
    asm("cvt.rn.bf16x2.f32 %0, %1, %2;" : "=r"(r) : "f"(b), "f"(a));
    return r;
}
__device__ __forceinline__ float bf_lo(uint32_t p) { return __uint_as_float(p << 16); }
__device__ __forceinline__ float bf_hi(uint32_t p) { return __uint_as_float(p & 0xFFFF0000u); }

__device__ __forceinline__ void mma_bf16(float4& d,
                                         uint32_t a0, uint32_t a1, uint32_t a2, uint32_t a3,
                                         uint32_t b0, uint32_t b1) {
    asm volatile("mma.sync.aligned.m16n8k16.row.col.f32.bf16.bf16.f32 "
                 "{%0,%1,%2,%3}, {%4,%5,%6,%7}, {%8,%9}, {%0,%1,%2,%3};"
                 : "+f"(d.x), "+f"(d.y), "+f"(d.z), "+f"(d.w)
                 : "r"(a0), "r"(a1), "r"(a2), "r"(a3), "r"(b0), "r"(b1));
}

__device__ __forceinline__ void ldsm_x4(uint32_t& r0, uint32_t& r1,
                                        uint32_t& r2, uint32_t& r3, uint32_t addr) {
    asm volatile("ldmatrix.sync.aligned.m8n8.x4.shared.b16 {%0,%1,%2,%3}, [%4];"
                 : "=r"(r0), "=r"(r1), "=r"(r2), "=r"(r3) : "r"(addr));
}

#define CP_ASYNC16(dst, src) \
    asm volatile("cp.async.ca.shared.global [%0], [%1], 16;" :: "r"(dst), "l"(src))
#define CP_ASYNC_WAIT_ALL() do {                              \
    asm volatile("cp.async.commit_group;");                   \
    asm volatile("cp.async.wait_group 0;" ::: "memory");      \
} while (0)

// ---------------------------------------------------------------------------
// Transpose + bf16-split W[256][128] -> g_Bh/g_Bl packed pairs   (launch #1)
// ---------------------------------------------------------------------------
__global__ void k_wsplit(const float* __restrict__ W) {
    int g = blockIdx.x * blockDim.x + threadIdx.x;
    if (g >= OUT_CH * 128) return;
    int n  = g >> 7;
    int kp = g & 127;
    float v0 = W[(size_t)(2 * kp)     * OUT_CH + n];
    float v1 = W[(size_t)(2 * kp + 1) * OUT_CH + n];
    float h0 = trunc_bf16(v0), h1 = trunc_bf16(v1);
    g_Bh[(size_t)n * 128 + kp] = pack_bf16x2(h0, h1);
    g_Bl[(size_t)n * 128 + kp] = pack_bf16x2(v0 - h0, v1 - h1);
}

// ---------------------------------------------------------------------------
// Detect edge_index dtype + deg init (self loop)    (launch #2)
// ---------------------------------------------------------------------------
__global__ void k_detect_init(const int* __restrict__ ei_words) {
    int i = blockIdx.x * blockDim.x + threadIdx.x;
    if (i < N_NODES) g_deg[i] = 1.0f;
    if (i == 0) {
        int all_zero = 1;
        for (int j = 0; j < 64; j++)
            if (ei_words[2 * j + 1] != 0) { all_zero = 0; break; }
        g_is64 = all_zero;
    }
}
__device__ __forceinline__ int edge_idx(const void* ei, int which, int e) {
    if (g_is64) return (int)((const long long*)ei)[(size_t)which * N_EDGES + e];
    return ((const int*)ei)[(size_t)which * N_EDGES + e];
}

__global__ void k_deg(const void* __restrict__ ei) {    // launch #3
    int e = blockIdx.x * blockDim.x + threadIdx.x;
    if (e < N_EDGES) atomicAdd(&g_deg[edge_idx(ei, 1, e)], 1.0f);
}

// ---------------------------------------------------------------------------
// bf16 3x-split GEMM, ldmatrix fragments + cp.async W staging.
// g_hb = bf16x2(x @ W). CTA 128x128, K-chunk 64.   (launch #4 — profiled)
// ---------------------------------------------------------------------------
#define XS_STRIDE 36
#define GSM_BYTES (4 * 128 * XS_STRIDE * 4)   // 73728

__global__ void __launch_bounds__(256, 2) k_gemm_mma(const float* __restrict__ x, int M) {
    extern __shared__ uint32_t smem_u[];
    uint32_t* xh = smem_u;
    uint32_t* xl = xh + 128 * XS_STRIDE;
    uint32_t* wh = xl + 128 * XS_STRIDE;
    uint32_t* wl = wh + 128 * XS_STRIDE;

    const int tid    = threadIdx.x;
    const int wid    = tid >> 5;
    const int lane   = tid & 31;
    const int gq     = lane >> 2;
    const int tq     = lane & 3;
    const int warp_m = wid >> 2;
    const int warp_n = wid & 3;
    const int row0   = blockIdx.x * 128;

    uint32_t smem_b;
    asm("{ .reg .u64 t; cvta.to.shared.u64 t, %1; cvt.u32.u64 %0, t; }"
        : "=r"(smem_b) : "l"(smem_u));
    const uint32_t xh_b = smem_b;
    const uint32_t xl_b = smem_b + 128 * XS_STRIDE * 4;
    const uint32_t wh_b = smem_b + 2 * 128 * XS_STRIDE * 4;
    const uint32_t wl_b = smem_b + 3 * 128 * XS_STRIDE * 4;

    // ldmatrix lane address components
    const int a_row  = (lane & 7) + ((lane >> 3) & 1) * 8;   // 0..15
    const int a_koff = ((lane >> 4) & 1) * 4;                // 0 or 4 (k-pairs)
    const int b_row  = (lane & 7) + ((lane >> 4) & 1) * 8;   // 0..15 within nfp block
    const int b_koff = ((lane >> 3) & 1) * 4;

    const uint32_t a_base = xh_b + (((warp_m * 64 + a_row) * XS_STRIDE) + a_koff) * 4;
    const uint32_t b_base = wh_b + (((warp_n * 32 + b_row) * XS_STRIDE) + b_koff) * 4;
    const uint32_t hl_off = 128 * XS_STRIDE * 4;   // hi -> lo array offset

    float4 acc[4][4];
#pragma unroll
    for (int i = 0; i < 4; i++)
#pragma unroll
        for (int j = 0; j < 4; j++) acc[i][j] = make_float4(0.f, 0.f, 0.f, 0.f);

    for (int c = 0; c < 4; c++) {
        // stage W chunk via cp.async: 128 n x 8 uint4 per array; 4 iters/thread
#pragma unroll
        for (int i = 0; i < 4; i++) {
            int idx = tid + i * 256;          // 0..1023
            int n   = idx >> 3;
            int f4  = idx & 7;
            size_t gofs = (size_t)n * 128 + c * 32 + f4 * 4;
            uint32_t so = ((n * XS_STRIDE) + f4 * 4) * 4;
            CP_ASYNC16(wh_b + so, g_Bh + gofs);
            CP_ASYNC16(wl_b + so, g_Bl + gofs);
        }
        // stage x chunk: 128 rows x 16 float4; 8/thread, split hi/lo
#pragma unroll
        for (int i = 0; i < 8; i++) {
            int idx = tid + i * 256;
            int m   = idx >> 4;
            int f4  = idx & 15;
            int gr  = row0 + m;
            float4 v = make_float4(0.f, 0.f, 0.f, 0.f);
            if (gr < M)
                v = *(const float4*)(x + (size_t)gr * IN_CH + c * 64 + f4 * 4);
            float h0 = trunc_bf16(v.x), h1 = trunc_bf16(v.y);
            float h2 = trunc_bf16(v.z), h3 = trunc_bf16(v.w);
            *(uint2*)(xh + m * XS_STRIDE + f4 * 2) =
                make_uint2(pack_bf16x2(h0, h1), pack_bf16x2(h2, h3));
            *(uint2*)(xl + m * XS_STRIDE + f4 * 2) =
                make_uint2(pack_bf16x2(v.x - h0, v.y - h1), pack_bf16x2(v.z - h2, v.w - h3));
        }
        CP_ASYNC_WAIT_ALL();
        __syncthreads();

#pragma unroll
        for (int s = 0; s < 4; s++) {
            const uint32_t s_off = s * 8 * 4;   // bytes
            // B fragments: nfp=0 covers nf0,nf1; nfp=1 covers nf2,nf3
            uint32_t bh[8], bl[8];
#pragma unroll
            for (int nfp = 0; nfp < 2; nfp++) {
                uint32_t ba = b_base + nfp * (16 * XS_STRIDE * 4) + s_off;
                ldsm_x4(bh[nfp * 4 + 0], bh[nfp * 4 + 1], bh[nfp * 4 + 2], bh[nfp * 4 + 3], ba);
                ldsm_x4(bl[nfp * 4 + 0], bl[nfp * 4 + 1], bl[nfp * 4 + 2], bl[nfp * 4 + 3], ba + hl_off);
            }
#pragma unroll
            for (int mf = 0; mf < 4; mf++) {
                uint32_t aa = a_base + mf * (16 * XS_STRIDE * 4) + s_off;
                uint32_t ah0, ah1, ah2, ah3, al0, al1, al2, al3;
                ldsm_x4(ah0, ah1, ah2, ah3, aa);
                ldsm_x4(al0, al1, al2, al3, aa + hl_off);
#pragma unroll
                for (int nf = 0; nf < 4; nf++) {
                    uint32_t b0h = bh[nf * 2], b1h = bh[nf * 2 + 1];
                    uint32_t b0l = bl[nf * 2], b1l = bl[nf * 2 + 1];
                    mma_bf16(acc[mf][nf], ah0, ah1, ah2, ah3, b0h, b1h);
                    mma_bf16(acc[mf][nf], ah0, ah1, ah2, ah3, b0l, b1l);
                    mma_bf16(acc[mf][nf], al0, al1, al2, al3, b0h, b1h);
                }
            }
        }
        __syncthreads();
    }

    // Store bf16x2(h) — dinv applied in gather.
#pragma unroll
    for (int mf = 0; mf < 4; mf++) {
        int rA = row0 + warp_m * 64 + mf * 16 + gq;
        int rB = rA + 8;
#pragma unroll
        for (int nf = 0; nf < 4; nf++) {
            int cp = warp_n * 16 + nf * 4 + tq;
            if (rA < M)
                g_hb[(size_t)rA * 64 + cp] = pack_bf16x2(acc[mf][nf].x, acc[mf][nf].y);
            if (rB < M)
                g_hb[(size_t)rB * 64 + cp] = pack_bf16x2(acc[mf][nf].z, acc[mf][nf].w);
        }
    }
}

// ---------------------------------------------------------------------------
// 3-pass exclusive scan of in-degree counts (deg-1) -> g_off, g_cursor; dinv.
// ---------------------------------------------------------------------------
__global__ void k_scan1() {
    __shared__ int sm[256];
    int tid = threadIdx.x;
    int i = blockIdx.x * 256 + tid;
    sm[tid] = (i < N_NODES) ? ((int)g_deg[i] - 1) : 0;
    __syncthreads();
#pragma unroll
    for (int o = 128; o; o >>= 1) {
        if (tid < o) sm[tid] += sm[tid + o];
        __syncthreads();
    }
    if (tid == 0) g_bsum[blockIdx.x] = sm[0];
}

__global__ void k_scan2() {
    __shared__ int sm[512];
    int t = threadIdx.x;
    int v0 = (t < NB) ? g_bsum[t] : 0;
    sm[t] = v0;
    __syncthreads();
#pragma unroll
    for (int o = 1; o < 512; o <<= 1) {
        int v = (t >= o) ? sm[t - o] : 0;
        __syncthreads();
        sm[t] += v;
        __syncthreads();
    }
    if (t < NB) g_boff[t] = sm[t] - v0;
}

__global__ void k_scan3() {
    __shared__ int sm[256];
    int tid = threadIdx.x;
    int i = blockIdx.x * 256 + tid;
    int cnt = (i < N_NODES) ? ((int)g_deg[i] - 1) : 0;
    sm[tid] = cnt;
    __syncthreads();
#pragma unroll
    for (int o = 1; o < 256; o <<= 1) {
        int v = (tid >= o) ? sm[tid - o] : 0;
        __syncthreads();
        sm[tid] += v;
        __syncthreads();
    }
    if (i < N_NODES) {
        int excl = sm[tid] - cnt + g_boff[blockIdx.x];
        g_off[i]    = excl;
        g_cursor[i] = excl;
        g_dinv[i]   = rsqrtf(g_deg[i]);
    }
}

// ---------------------------------------------------------------------------
__global__ void k_scatter(const void* __restrict__ ei) {
    int e = blockIdx.x * blockDim.x + threadIdx.x;
    if (e >= N_EDGES) return;
    int c = edge_idx(ei, 1, e);
    int r = edge_idx(ei, 0, e);
    int pos = atomicAdd(&g_cursor[c], 1);
    g_src[pos] = r;
}

// ---------------------------------------------------------------------------
// Fused gather + epilogue: one warp per node, bf16x2 rows, 8-deep prefetch.
// ---------------------------------------------------------------------------
__global__ void __launch_bounds__(256) k_gather_epi(const float* __restrict__ b,
                                                    float* __restrict__ out) {
    int wid  = threadIdx.x >> 5;
    int lane = threadIdx.x & 31;
    int node = blockIdx.x * 8 + wid;
    if (node >= N_NODES) return;

    int s0  = g_off[node];
    int cnt = (int)g_deg[node] - 1;
    float dvc = g_dinv[node];

    uint2 sp = ((const uint2*)(g_hb + (size_t)node * 64))[lane];
    float4 sum = make_float4(bf_lo(sp.x) * dvc, bf_hi(sp.x) * dvc,
                             bf_lo(sp.y) * dvc, bf_hi(sp.y) * dvc);

    int i = 0;
    for (; i + 8 <= cnt; i += 8) {
        int   si[8];
        float dv[8];
        uint2 p[8];
#pragma unroll
        for (int j = 0; j < 8; j++) si[j] = __ldg(&g_src[s0 + i + j]);
#pragma unroll
        for (int j = 0; j < 8; j++) dv[j] = __ldg(&g_dinv[si[j]]);
#pragma unroll
        for (int j = 0; j < 8; j++)
            p[j] = __ldg(&((const uint2*)(g_hb + (size_t)si[j] * 64))[lane]);
#pragma unroll
        for (int j = 0; j < 8; j++) {
            sum.x += bf_lo(p[j].x) * dv[j];
            sum.y += bf_hi(p[j].x) * dv[j];
            sum.z += bf_lo(p[j].y) * dv[j];
            sum.w += bf_hi(p[j].y) * dv[j];
        }
    }
    for (; i < cnt; i++) {
        int s = __ldg(&g_src[s0 + i]);
        float dv = __ldg(&g_dinv[s]);
        uint2 p = __ldg(&((const uint2*)(g_hb + (size_t)s * 64))[lane]);
        sum.x += bf_lo(p.x) * dv; sum.y += bf_hi(p.x) * dv;
        sum.z += bf_lo(p.y) * dv; sum.w += bf_hi(p.y) * dv;
    }

    const float4 bv = ((const float4*)b)[lane];
    float4 v;
    v.x = sum.x * dvc + bv.x;
    v.y = sum.y * dvc + bv.y;
    v.z = sum.z * dvc + bv.z;
    v.w = sum.w * dvc + bv.w;

    float mn = fminf(fminf(v.x, v.y), fminf(v.z, v.w));
    float mx = fmaxf(fmaxf(v.x, v.y), fmaxf(v.z, v.w));
#pragma unroll
    for (int o = 16; o; o >>= 1) {
        mn = fminf(mn, __shfl_xor_sync(0xffffffffu, mn, o));
        mx = fmaxf(mx, __shfl_xor_sync(0xffffffffu, mx, o));
    }

    float inv = 1.0f / (mx - mn);
    float4 z;
    z.x = (v.x - mn) * inv;
    z.y = (v.y - mn) * inv;
    z.z = (v.z - mn) * inv;
    z.w = (v.w - mn) * inv;

    float ss = z.x * z.x + z.y * z.y + z.z * z.z + z.w * z.w;
#pragma unroll
    for (int o = 16; o; o >>= 1)
        ss += __shfl_xor_sync(0xffffffffu, ss, o);

    float rn = 1.0f / fmaxf(sqrtf(ss), 1e-12f);
    z.x *= rn; z.y *= rn; z.z *= rn; z.w *= rn;

    ((float4*)out)[(size_t)node * 32 + lane] = z;
}

// ---------------------------------------------------------------------------
extern "C" void kernel_launch(void* const* d_in, const int* in_sizes, int n_in,
                              void* d_out, int out_size) {
    const float* x   = (const float*)d_in[0];
    const void*  ei  = d_in[1];
    const float* W   = (const float*)d_in[2];
    const float* b   = (const float*)d_in[3];
    float*       out = (float*)d_out;

    (void)in_sizes; (void)n_in; (void)out_size;

    cudaFuncSetAttribute(k_gemm_mma, cudaFuncAttributeMaxDynamicSharedMemorySize, GSM_BYTES);

    k_wsplit     <<<(OUT_CH * 128 + 255) / 256, 256>>>(W);     // 1
    k_detect_init<<<NB, 256>>>((const int*)ei);                // 2
    k_deg        <<<(N_EDGES + 255) / 256, 256>>>(ei);         // 3
    k_gemm_mma   <<<(N_NODES + 127) / 128, 256, GSM_BYTES>>>(x, N_NODES);  // 4 (profiled)
    k_scan1      <<<NB, 256>>>();                              // 5
    k_scan2      <<<1, 512>>>();                               // 6
    k_scan3      <<<NB, 256>>>();                              // 7
    k_scatter    <<<(N_EDGES + 255) / 256, 256>>>(ei);         // 8
    k_gather_epi <<<(N_NODES + 7) / 8, 256>>>(b, out);         // 9
}

// round 11
// speedup vs baseline: 4.1750x; 1.0138x over previous
#include <cuda_runtime.h>
#include <cstdint>

#define N_NODES 100000
#define N_EDGES 1600000
#define IN_CH   256
#define OUT_CH  128
#define NB      ((N_NODES + 255) / 256)   // 391
#define EDGEW   148                       // edge-role blocks per fused launch
#define GEMM_HALF_BLOCKS 391              // 391*128 = 50048 rows per half
#define ROWS_A  (GEMM_HALF_BLOCKS * 128)

// ---------------------------------------------------------------------------
// Scratch (static device globals — allocation-free per harness rules)
// ---------------------------------------------------------------------------
__device__ float g_deg[N_NODES];
__device__ float g_dinv[N_NODES];
__device__ __align__(16) uint32_t g_hb[(size_t)N_NODES * 64];   // h, bf16x2
__device__ __align__(16) uint32_t g_Bh[OUT_CH * 128];           // W^T hi bf16x2 [n][kpair]
__device__ __align__(16) uint32_t g_Bl[OUT_CH * 128];           // W^T lo bf16x2 [n][kpair]
__device__ int   g_is64;
__device__ int   g_bsum[NB];
__device__ int   g_off[N_NODES];
__device__ int   g_cursor[N_NODES];
__device__ int   g_src[N_EDGES];

// ---------------------------------------------------------------------------
// helpers
// ---------------------------------------------------------------------------
__device__ __forceinline__ float trunc_bf16(float v) {
    return __uint_as_float(__float_as_uint(v) & 0xFFFF0000u);
}
__device__ __forceinline__ uint32_t pack_bf16x2(float a, float b) {
    uint32_t r;
    asm("cvt.rn.bf16x2.f32 %0, %1, %2;" : "=r"(r) : "f"(b), "f"(a));
    return r;
}
__device__ __forceinline__ float bf_lo(uint32_t p) { return __uint_as_float(p << 16); }
__device__ __forceinline__ float bf_hi(uint32_t p) { return __uint_as_float(p & 0xFFFF0000u); }

__device__ __forceinline__ void mma_bf16(float4& d,
                                         uint32_t a0, uint32_t a1, uint32_t a2, uint32_t a3,
                                         uint32_t b0, uint32_t b1) {
    asm volatile("mma.sync.aligned.m16n8k16.row.col.f32.bf16.bf16.f32 "
                 "{%0,%1,%2,%3}, {%4,%5,%6,%7}, {%8,%9}, {%0,%1,%2,%3};"
                 : "+f"(d.x), "+f"(d.y), "+f"(d.z), "+f"(d.w)
                 : "r"(a0), "r"(a1), "r"(a2), "r"(a3), "r"(b0), "r"(b1));
}

__device__ __forceinline__ void ldsm_x4(uint32_t& r0, uint32_t& r1,
                                        uint32_t& r2, uint32_t& r3, uint32_t addr) {
    asm volatile("ldmatrix.sync.aligned.m8n8.x4.shared.b16 {%0,%1,%2,%3}, [%4];"
                 : "=r"(r0), "=r"(r1), "=r"(r2), "=r"(r3) : "r"(addr));
}

#define CP_ASYNC16(dst, src) \
    asm volatile("cp.async.ca.shared.global [%0], [%1], 16;" :: "r"(dst), "l"(src))
#define CP_ASYNC_WAIT_ALL() do {                              \
    asm volatile("cp.async.commit_group;");                   \
    asm volatile("cp.async.wait_group 0;" ::: "memory");      \
} while (0)

__device__ __forceinline__ int edge_idx(const void* ei, int which, int e) {
    if (g_is64) return (int)((const long long*)ei)[(size_t)which * N_EDGES + e];
    return ((const int*)ei)[(size_t)which * N_EDGES + e];
}

// ---------------------------------------------------------------------------
// Pre-pass: W transpose+split, deg init, dtype detect.       (launch #1)
// ---------------------------------------------------------------------------
__global__ void k_pre(const float* __restrict__ W, const int* __restrict__ ei_words) {
    int i = blockIdx.x * blockDim.x + threadIdx.x;
    if (i < OUT_CH * 128) {
        int n  = i >> 7;
        int kp = i & 127;
        float v0 = W[(size_t)(2 * kp)     * OUT_CH + n];
        float v1 = W[(size_t)(2 * kp + 1) * OUT_CH + n];
        float h0 = trunc_bf16(v0), h1 = trunc_bf16(v1);
        g_Bh[(size_t)n * 128 + kp] = pack_bf16x2(h0, h1);
        g_Bl[(size_t)n * 128 + kp] = pack_bf16x2(v0 - h0, v1 - h1);
    }
    if (i < N_NODES) g_deg[i] = 1.0f;     // self loop
    if (i == 0) {
        int all_zero = 1;
        for (int j = 0; j < 64; j++)
            if (ei_words[2 * j + 1] != 0) { all_zero = 0; break; }
        g_is64 = all_zero;
    }
}

// ---------------------------------------------------------------------------
// Fused GEMM half + edge work.
// Blocks [0, EDGEW): grid-stride edge role (deg if !do_scatter, else scatter).
// Blocks [EDGEW, EDGEW+391): bf16 3x-split mma GEMM, rows row_base + ...
// (launches #2 and #5)
// ---------------------------------------------------------------------------
#define XS_STRIDE 36
#define GSM_BYTES (4 * 128 * XS_STRIDE * 4)   // 73728

__global__ void __launch_bounds__(256, 2) k_gemm_fused(const float* __restrict__ x,
                                                       const void* __restrict__ ei,
                                                       int row_base, int do_scatter, int M) {
    // ---------------- edge role ----------------
    if (blockIdx.x < EDGEW) {
        int t      = blockIdx.x * 256 + threadIdx.x;
        int stride = EDGEW * 256;
        if (!do_scatter) {
            for (int e = t; e < N_EDGES; e += stride)
                atomicAdd(&g_deg[edge_idx(ei, 1, e)], 1.0f);
        } else {
            for (int e = t; e < N_EDGES; e += stride) {
                int c = edge_idx(ei, 1, e);
                int r = edge_idx(ei, 0, e);
                g_src[atomicAdd(&g_cursor[c], 1)] = r;
            }
        }
        return;
    }

    // ---------------- GEMM role ----------------
    extern __shared__ uint32_t smem_u[];
    uint32_t* xh = smem_u;
    uint32_t* xl = xh + 128 * XS_STRIDE;

    const int tid    = threadIdx.x;
    const int wid    = tid >> 5;
    const int lane   = tid & 31;
    const int gq     = lane >> 2;
    const int tq     = lane & 3;
    const int warp_m = wid >> 2;
    const int warp_n = wid & 3;
    const int row0   = row_base + (blockIdx.x - EDGEW) * 128;

    uint32_t smem_b;
    asm("{ .reg .u64 t; cvta.to.shared.u64 t, %1; cvt.u32.u64 %0, t; }"
        : "=r"(smem_b) : "l"(smem_u));
    const uint32_t xh_b = smem_b;
    const uint32_t wh_b = smem_b + 2 * 128 * XS_STRIDE * 4;
    const uint32_t wl_b = smem_b + 3 * 128 * XS_STRIDE * 4;

    const int a_row  = (lane & 7) + ((lane >> 3) & 1) * 8;
    const int a_koff = ((lane >> 4) & 1) * 4;
    const int b_row  = (lane & 7) + ((lane >> 4) & 1) * 8;
    const int b_koff = ((lane >> 3) & 1) * 4;

    const uint32_t a_base = xh_b + (((warp_m * 64 + a_row) * XS_STRIDE) + a_koff) * 4;
    const uint32_t b_base = wh_b + (((warp_n * 32 + b_row) * XS_STRIDE) + b_koff) * 4;
    const uint32_t hl_off = 128 * XS_STRIDE * 4;

    float4 acc[4][4];
#pragma unroll
    for (int i = 0; i < 4; i++)
#pragma unroll
        for (int j = 0; j < 4; j++) acc[i][j] = make_float4(0.f, 0.f, 0.f, 0.f);

    for (int c = 0; c < 4; c++) {
        // stage W chunk via cp.async
#pragma unroll
        for (int i = 0; i < 4; i++) {
            int idx = tid + i * 256;
            int n   = idx >> 3;
            int f4  = idx & 7;
            size_t gofs = (size_t)n * 128 + c * 32 + f4 * 4;
            uint32_t so = ((n * XS_STRIDE) + f4 * 4) * 4;
            CP_ASYNC16(wh_b + so, g_Bh + gofs);
            CP_ASYNC16(wl_b + so, g_Bl + gofs);
        }
        // stage x chunk: split hi/lo
#pragma unroll
        for (int i = 0; i < 8; i++) {
            int idx = tid + i * 256;
            int m   = idx >> 4;
            int f4  = idx & 15;
            int gr  = row0 + m;
            float4 v = make_float4(0.f, 0.f, 0.f, 0.f);
            if (gr < M)
                v = *(const float4*)(x + (size_t)gr * IN_CH + c * 64 + f4 * 4);
            float h0 = trunc_bf16(v.x), h1 = trunc_bf16(v.y);
            float h2 = trunc_bf16(v.z), h3 = trunc_bf16(v.w);
            *(uint2*)(xh + m * XS_STRIDE + f4 * 2) =
                make_uint2(pack_bf16x2(h0, h1), pack_bf16x2(h2, h3));
            *(uint2*)(xl + m * XS_STRIDE + f4 * 2) =
                make_uint2(pack_bf16x2(v.x - h0, v.y - h1), pack_bf16x2(v.z - h2, v.w - h3));
        }
        CP_ASYNC_WAIT_ALL();
        __syncthreads();

#pragma unroll
        for (int s = 0; s < 4; s++) {
            const uint32_t s_off = s * 8 * 4;
            uint32_t bh[8], bl[8];
#pragma unroll
            for (int nfp = 0; nfp < 2; nfp++) {
                uint32_t ba = b_base + nfp * (16 * XS_STRIDE * 4) + s_off;
                ldsm_x4(bh[nfp * 4 + 0], bh[nfp * 4 + 1], bh[nfp * 4 + 2], bh[nfp * 4 + 3], ba);
                ldsm_x4(bl[nfp * 4 + 0], bl[nfp * 4 + 1], bl[nfp * 4 + 2], bl[nfp * 4 + 3], ba + hl_off);
            }
#pragma unroll
            for (int mf = 0; mf < 4; mf++) {
                uint32_t aa = a_base + mf * (16 * XS_STRIDE * 4) + s_off;
                uint32_t ah0, ah1, ah2, ah3, al0, al1, al2, al3;
                ldsm_x4(ah0, ah1, ah2, ah3, aa);
                ldsm_x4(al0, al1, al2, al3, aa + hl_off);
#pragma unroll
                for (int nf = 0; nf < 4; nf++) {
                    uint32_t b0h = bh[nf * 2], b1h = bh[nf * 2 + 1];
                    uint32_t b0l = bl[nf * 2], b1l = bl[nf * 2 + 1];
                    mma_bf16(acc[mf][nf], ah0, ah1, ah2, ah3, b0h, b1h);
                    mma_bf16(acc[mf][nf], ah0, ah1, ah2, ah3, b0l, b1l);
                    mma_bf16(acc[mf][nf], al0, al1, al2, al3, b0h, b1h);
                }
            }
        }
        __syncthreads();
    }

#pragma unroll
    for (int mf = 0; mf < 4; mf++) {
        int rA = row0 + warp_m * 64 + mf * 16 + gq;
        int rB = rA + 8;
#pragma unroll
        for (int nf = 0; nf < 4; nf++) {
            int cp = warp_n * 16 + nf * 4 + tq;
            if (rA < M)
                g_hb[(size_t)rA * 64 + cp] = pack_bf16x2(acc[mf][nf].x, acc[mf][nf].y);
            if (rB < M)
                g_hb[(size_t)rB * 64 + cp] = pack_bf16x2(acc[mf][nf].z, acc[mf][nf].w);
        }
    }
}

// ---------------------------------------------------------------------------
// scan1: per-block sums of (deg-1).                          (launch #3)
// ---------------------------------------------------------------------------
__global__ void k_scan1() {
    __shared__ int sm[256];
    int tid = threadIdx.x;
    int i = blockIdx.x * 256 + tid;
    sm[tid] = (i < N_NODES) ? ((int)g_deg[i] - 1) : 0;
    __syncthreads();
#pragma unroll
    for (int o = 128; o; o >>= 1) {
        if (tid < o) sm[tid] += sm[tid + o];
        __syncthreads();
    }
    if (tid == 0) g_bsum[blockIdx.x] = sm[0];
}

// ---------------------------------------------------------------------------
// scan23 merged: each block privately reduces its offset from g_bsum,
// then does the local inclusive scan -> g_off, g_cursor, dinv.  (launch #4)
// ---------------------------------------------------------------------------
__global__ void k_scan23() {
    __shared__ int sm[256];
    __shared__ int s_boff;
    int tid = threadIdx.x;
    int b   = blockIdx.x;

    // block offset = sum of g_bsum[0..b)
    int acc = 0;
    for (int j = tid; j < b; j += 256) acc += g_bsum[j];
    sm[tid] = acc;
    __syncthreads();
#pragma unroll
    for (int o = 128; o; o >>= 1) {
        if (tid < o) sm[tid] += sm[tid + o];
        __syncthreads();
    }
    if (tid == 0) s_boff = sm[0];
    __syncthreads();
    int boff = s_boff;
    __syncthreads();

    // local inclusive scan
    int i = b * 256 + tid;
    int cnt = (i < N_NODES) ? ((int)g_deg[i] - 1) : 0;
    sm[tid] = cnt;
    __syncthreads();
#pragma unroll
    for (int o = 1; o < 256; o <<= 1) {
        int v = (tid >= o) ? sm[tid - o] : 0;
        __syncthreads();
        sm[tid] += v;
        __syncthreads();
    }
    if (i < N_NODES) {
        int excl = sm[tid] - cnt + boff;
        g_off[i]    = excl;
        g_cursor[i] = excl;
        g_dinv[i]   = rsqrtf(g_deg[i]);
    }
}

// ---------------------------------------------------------------------------
// Fused gather + epilogue: one warp per node, bf16x2 rows, 8-deep prefetch.
// (launch #6)
// ---------------------------------------------------------------------------
__global__ void __launch_bounds__(256) k_gather_epi(const float* __restrict__ b,
                                                    float* __restrict__ out) {
    int wid  = threadIdx.x >> 5;
    int lane = threadIdx.x & 31;
    int node = blockIdx.x * 8 + wid;
    if (node >= N_NODES) return;

    int s0  = g_off[node];
    int cnt = (int)g_deg[node] - 1;
    float dvc = g_dinv[node];

    uint2 sp = ((const uint2*)(g_hb + (size_t)node * 64))[lane];
    float4 sum = make_float4(bf_lo(sp.x) * dvc, bf_hi(sp.x) * dvc,
                             bf_lo(sp.y) * dvc, bf_hi(sp.y) * dvc);

    int i = 0;
    for (; i + 8 <= cnt; i += 8) {
        int   si[8];
        float dv[8];
        uint2 p[8];
#pragma unroll
        for (int j = 0; j < 8; j++) si[j] = __ldg(&g_src[s0 + i + j]);
#pragma unroll
        for (int j = 0; j < 8; j++) dv[j] = __ldg(&g_dinv[si[j]]);
#pragma unroll
        for (int j = 0; j < 8; j++)
            p[j] = __ldg(&((const uint2*)(g_hb + (size_t)si[j] * 64))[lane]);
#pragma unroll
        for (int j = 0; j < 8; j++) {
            sum.x += bf_lo(p[j].x) * dv[j];
            sum.y += bf_hi(p[j].x) * dv[j];
            sum.z += bf_lo(p[j].y) * dv[j];
            sum.w += bf_hi(p[j].y) * dv[j];
        }
    }
    for (; i < cnt; i++) {
        int s = __ldg(&g_src[s0 + i]);
        float dv = __ldg(&g_dinv[s]);
        uint2 p = __ldg(&((const uint2*)(g_hb + (size_t)s * 64))[lane]);
        sum.x += bf_lo(p.x) * dv; sum.y += bf_hi(p.x) * dv;
        sum.z += bf_lo(p.y) * dv; sum.w += bf_hi(p.y) * dv;
    }

    const float4 bv = ((const float4*)b)[lane];
    float4 v;
    v.x = sum.x * dvc + bv.x;
    v.y = sum.y * dvc + bv.y;
    v.z = sum.z * dvc + bv.z;
    v.w = sum.w * dvc + bv.w;

    float mn = fminf(fminf(v.x, v.y), fminf(v.z, v.w));
    float mx = fmaxf(fmaxf(v.x, v.y), fmaxf(v.z, v.w));
#pragma unroll
    for (int o = 16; o; o >>= 1) {
        mn = fminf(mn, __shfl_xor_sync(0xffffffffu, mn, o));
        mx = fmaxf(mx, __shfl_xor_sync(0xffffffffu, mx, o));
    }

    float inv = 1.0f / (mx - mn);
    float4 z;
    z.x = (v.x - mn) * inv;
    z.y = (v.y - mn) * inv;
    z.z = (v.z - mn) * inv;
    z.w = (v.w - mn) * inv;

    float ss = z.x * z.x + z.y * z.y + z.z * z.z + z.w * z.w;
#pragma unroll
    for (int o = 16; o; o >>= 1)
        ss += __shfl_xor_sync(0xffffffffu, ss, o);

    float rn = 1.0f / fmaxf(sqrtf(ss), 1e-12f);
    z.x *= rn; z.y *= rn; z.z *= rn; z.w *= rn;

    ((float4*)out)[(size_t)node * 32 + lane] = z;
}

// ---------------------------------------------------------------------------
extern "C" void kernel_launch(void* const* d_in, const int* in_sizes, int n_in,
                              void* d_out, int out_size) {
    const float* x   = (const float*)d_in[0];
    const void*  ei  = d_in[1];
    const float* W   = (const float*)d_in[2];
    const float* b   = (const float*)d_in[3];
    float*       out = (float*)d_out;

    (void)in_sizes; (void)n_in; (void)out_size;

    cudaFuncSetAttribute(k_gemm_fused, cudaFuncAttributeMaxDynamicSharedMemorySize, GSM_BYTES);

    const int fused_grid = EDGEW + GEMM_HALF_BLOCKS;

    k_pre       <<<NB, 256>>>(W, (const int*)ei);                               // 1
    k_gemm_fused<<<fused_grid, 256, GSM_BYTES>>>(x, ei, 0, 0, N_NODES);         // 2: gemm rows [0,50048) + deg
    k_scan1     <<<NB, 256>>>();                                                // 3
    k_scan23    <<<NB, 256>>>();                                                // 4 (profiled)
    k_gemm_fused<<<fused_grid, 256, GSM_BYTES>>>(x, ei, ROWS_A, 1, N_NODES);    // 5: gemm rows [50048,100000) + scatter
    k_gather_epi<<<(N_NODES + 7) / 8, 256>>>(b, out);                           // 6
}